// round 10
// baseline (speedup 1.0000x reference)
#include <cuda_runtime.h>
#include <math.h>

#define N_NODES 100000
#define E_MAX   1600000
#define FULL    0xffffffffu
#define N4      (N_NODES / 4)        // 25000 int4 groups
#define SCAN_B  ((N4 + 1023) / 1024) // 25 scan blocks

// ---------------- scratch (static __device__ — no dynamic alloc) ----------------
__device__ int   g_deg[N_NODES + 4];
__device__ int   g_off[N_NODES + 4];
__device__ int   g_cur[N_NODES + 4];
__device__ int   g_csr[E_MAX];
__device__ int   g_blk[SCAN_B];

__device__ float g_xl1[N_NODES * 128];  // x @ W1
__device__ float g_as1[N_NODES * 8];    // a_src layer1
__device__ float g_ad1[N_NODES * 8];    // a_dst layer1
__device__ float g_xl2[N_NODES * 64];   // h @ W2 (written by fused agg1)
__device__ float g_as2[N_NODES];
__device__ float g_ad2[N_NODES];

__device__ __forceinline__ float lrelu(float x) { return x > 0.f ? x : 0.2f * x; }
__device__ __forceinline__ float elu_f(float x) { return x > 0.f ? x : expm1f(x); }

// packed f32x2 helpers (FFMA2 — PTX-only, doubles fp32 FMA throughput on sm_103a)
__device__ __forceinline__ unsigned long long pk2(float lo, float hi) {
    unsigned long long r;
    asm("mov.b64 %0, {%1, %2};" : "=l"(r) : "f"(lo), "f"(hi));
    return r;
}
__device__ __forceinline__ void upk2(unsigned long long v, float& lo, float& hi) {
    asm("mov.b64 {%0, %1}, %2;" : "=f"(lo), "=f"(hi) : "l"(v));
}
__device__ __forceinline__ unsigned long long fma2(unsigned long long a,
                                                   unsigned long long b,
                                                   unsigned long long c) {
    unsigned long long d;
    asm("fma.rn.f32x2 %0, %1, %2, %3;" : "=l"(d) : "l"(a), "l"(b), "l"(c));
    return d;
}

// ---------------- CSR build ----------------
__global__ void k_zero() {
    int i = blockIdx.x * blockDim.x + threadIdx.x;
    if (i < N_NODES + 4) g_deg[i] = 0;
}

__global__ void k_hist(const int* __restrict__ ei, int E) {
    int t = blockIdx.x * blockDim.x + threadIdx.x;
    int n4 = E >> 2;
    const int4* d4 = (const int4*)(ei + E);
    if (t < n4) {
        int4 v = d4[t];
        atomicAdd(&g_deg[v.x], 1);
        atomicAdd(&g_deg[v.y], 1);
        atomicAdd(&g_deg[v.z], 1);
        atomicAdd(&g_deg[v.w], 1);
    } else if (t == n4) {
        for (int e = n4 * 4; e < E; e++) atomicAdd(&g_deg[ei[E + e]], 1);
    }
}

// ---- multi-block scan: phase 1 — per-block exclusive scan + block totals ----
__global__ void __launch_bounds__(1024) k_scan1() {
    __shared__ int warp_sums[32];
    int tid = threadIdx.x, lane = tid & 31, wid = tid >> 5;
    int i = blockIdx.x * 1024 + tid;
    const int4* deg4 = (const int4*)g_deg;
    int4* off4 = (int4*)g_off;

    int4 v = (i < N4) ? deg4[i] : make_int4(0, 0, 0, 0);
    int tot = v.x + v.y + v.z + v.w;
    int xs = tot;
    #pragma unroll
    for (int o = 1; o < 32; o <<= 1) {
        int t = __shfl_up_sync(FULL, xs, o);
        if (lane >= o) xs += t;
    }
    if (lane == 31) warp_sums[wid] = xs;
    __syncthreads();
    if (wid == 0) {
        int ws = warp_sums[lane];
        #pragma unroll
        for (int o = 1; o < 32; o <<= 1) {
            int t = __shfl_up_sync(FULL, ws, o);
            if (lane >= o) ws += t;
        }
        warp_sums[lane] = ws;
    }
    __syncthreads();
    int incl = xs + (wid > 0 ? warp_sums[wid - 1] : 0);
    int b0 = incl - tot;
    if (i < N4) {
        int4 o;
        o.x = b0;
        o.y = b0 + v.x;
        o.z = o.y + v.y;
        o.w = o.z + v.z;
        off4[i] = o;
    }
    if (tid == 0) g_blk[blockIdx.x] = warp_sums[31];
}

// ---- scan phase 2+3 merged ----
__global__ void __launch_bounds__(1024) k_scan3() {
    __shared__ int s_off[32];
    int tid = threadIdx.x;
    if (tid < 32) {
        int t = (tid < SCAN_B) ? g_blk[tid] : 0;
        int xs = t;
        #pragma unroll
        for (int o = 1; o < 32; o <<= 1) {
            int u = __shfl_up_sync(FULL, xs, o);
            if (tid >= o) xs += u;
        }
        s_off[tid] = xs - t;
        if (blockIdx.x == 0 && tid == 31) g_off[N_NODES] = xs;
    }
    __syncthreads();
    int i = blockIdx.x * 1024 + tid;
    if (i < N4) {
        int add = s_off[blockIdx.x];
        int4* off4 = (int4*)g_off;
        int4* cur4 = (int4*)g_cur;
        int4 o = off4[i];
        o.x += add; o.y += add; o.z += add; o.w += add;
        off4[i] = o;
        cur4[i] = o;
    }
}

__global__ void k_scatter(const int* __restrict__ ei, int E) {
    int t = blockIdx.x * blockDim.x + threadIdx.x;
    int n4 = E >> 2;
    const int4* s4 = (const int4*)ei;
    const int4* d4 = (const int4*)(ei + E);
    if (t < n4) {
        int4 s = s4[t];
        int4 d = d4[t];
        g_csr[atomicAdd(&g_cur[d.x], 1)] = s.x;
        g_csr[atomicAdd(&g_cur[d.y], 1)] = s.y;
        g_csr[atomicAdd(&g_cur[d.z], 1)] = s.z;
        g_csr[atomicAdd(&g_cur[d.w], 1)] = s.w;
    } else if (t == n4) {
        for (int e = n4 * 4; e < E; e++)
            g_csr[atomicAdd(&g_cur[ei[E + e]], 1)] = ei[e];
    }
}

// ---------------- GEMM1 + att1 fused ----------------
__global__ void __launch_bounds__(128) k_gemm1att1(const float* __restrict__ x,
                                                   const float* __restrict__ W,
                                                   const float* __restrict__ asv,
                                                   const float* __restrict__ adv) {
    __shared__ __align__(16) float sxT[128][36];
    int c = threadIdx.x;
    int row0 = blockIdx.x * 32;
    #pragma unroll 8
    for (int r = 0; r < 32; r++)
        sxT[c][r] = x[(row0 + r) * 128 + c];
    __syncthreads();

    unsigned long long acc[16];
    #pragma unroll
    for (int i = 0; i < 16; i++) acc[i] = 0ull;

    #pragma unroll 4
    for (int k = 0; k < 128; k++) {
        float w = W[k * 128 + c];
        unsigned long long w2 = pk2(w, w);
        const float4* col4 = (const float4*)&sxT[k][0];
        #pragma unroll
        for (int i = 0; i < 8; i++) {
            float4 a = col4[i];
            acc[2 * i]     = fma2(pk2(a.x, a.y), w2, acc[2 * i]);
            acc[2 * i + 1] = fma2(pk2(a.z, a.w), w2, acc[2 * i + 1]);
        }
    }

    float as_c = asv[c], ad_c = adv[c];
    int head = c >> 4, l16 = c & 15;
    #pragma unroll
    for (int i = 0; i < 16; i++) {
        float o0, o1;
        upk2(acc[i], o0, o1);
        g_xl1[(row0 + 2 * i) * 128 + c] = o0;
        g_xl1[(row0 + 2 * i + 1) * 128 + c] = o1;
        float s0 = o0 * as_c, d0 = o0 * ad_c;
        float s1 = o1 * as_c, d1 = o1 * ad_c;
        #pragma unroll
        for (int ofs = 1; ofs < 16; ofs <<= 1) {
            s0 += __shfl_xor_sync(FULL, s0, ofs);
            d0 += __shfl_xor_sync(FULL, d0, ofs);
            s1 += __shfl_xor_sync(FULL, s1, ofs);
            d1 += __shfl_xor_sync(FULL, d1, ofs);
        }
        if (l16 == 0) {
            g_as1[(row0 + 2 * i) * 8 + head] = s0;
            g_ad1[(row0 + 2 * i) * 8 + head] = d0;
            g_as1[(row0 + 2 * i + 1) * 8 + head] = s1;
            g_ad1[(row0 + 2 * i + 1) * 8 + head] = d1;
        }
    }
}

// ---------------- layer-1 aggregation + layer-2 projection FUSED ----------------
// One warp per node. After computing h = elu(softmax-agg + b1) (held 4/lane),
// the warp stages h in shared and directly computes xl2 = h @ W2 plus the
// layer-2 attention logits — g_h never exists, gemm2att2 launch eliminated.
__global__ void __launch_bounds__(256) k_agg1f(const float* __restrict__ b1,
                                               const float* __restrict__ W2,
                                               const float* __restrict__ asv2,
                                               const float* __restrict__ adv2) {
    __shared__ __align__(16) float sh[8][128];
    int gw = (blockIdx.x * blockDim.x + threadIdx.x) >> 5;
    if (gw >= N_NODES) return;
    int wib = (threadIdx.x >> 5);  // warp within block (0..7)
    int lane = threadIdx.x & 31;
    int dst = gw;
    int beg = g_off[dst], end = g_off[dst + 1];
    int h = lane & 7, g = lane >> 3;
    int col = lane << 2, hs = lane >> 2;

    float adst = g_ad1[dst * 8 + h];
    float wself = __expf(lrelu(g_as1[dst * 8 + h] + adst));
    float denom = (g == 0) ? wself : 0.f;   // once per 8-lane residue class
    float wself_sel = __shfl_sync(FULL, wself, hs);
    float4 xv = *(const float4*)&g_xl1[dst * 128 + col];
    unsigned long long ws2 = pk2(wself_sel, wself_sel);
    unsigned long long a01 = fma2(pk2(xv.x, xv.y), ws2, 0ull);
    unsigned long long a23 = fma2(pk2(xv.z, xv.w), ws2, 0ull);

    for (int base = beg; base < end; base += 32) {
        int mycsr = (base + lane < end) ? g_csr[base + lane] : 0;
        int n = min(32, end - base);
        for (int sub = 0; sub < n; sub += 4) {
            int src_g = __shfl_sync(FULL, mycsr, sub + g);
            float e = lrelu(__ldg(&g_as1[src_g * 8 + h]) + adst);
            float w = ((sub + g) < n) ? __expf(e) : 0.f;
            denom += w;   // identical within 8-lane group; xor-8/16 tree counts once
            #pragma unroll
            for (int j = 0; j < 4; j++) {
                if (sub + j < n) {   // warp-uniform condition
                    int srcj = __shfl_sync(FULL, mycsr, sub + j);
                    float wsel = __shfl_sync(FULL, w, (j << 3) + hs);
                    float4 v = *(const float4*)&g_xl1[srcj * 128 + col];
                    unsigned long long w2 = pk2(wsel, wsel);
                    a01 = fma2(pk2(v.x, v.y), w2, a01);
                    a23 = fma2(pk2(v.z, v.w), w2, a23);
                }
            }
        }
    }
    denom += __shfl_xor_sync(FULL, denom, 8);
    denom += __shfl_xor_sync(FULL, denom, 16);
    float invS = 1.f / (denom + 1e-16f);
    float invS_sel = __shfl_sync(FULL, invS, hs);

    float ax, ay, az, aw;
    upk2(a01, ax, ay);
    upk2(a23, az, aw);
    float4 o;
    o.x = elu_f(ax * invS_sel + b1[col + 0]);
    o.y = elu_f(ay * invS_sel + b1[col + 1]);
    o.z = elu_f(az * invS_sel + b1[col + 2]);
    o.w = elu_f(aw * invS_sel + b1[col + 3]);

    // ---- fused layer-2 projection: xl2 = h @ W2, att2 logits ----
    *(float4*)&sh[wib][col] = o;
    __syncwarp();

    int c2 = lane << 1;  // this lane computes output cols c2, c2+1
    unsigned long long acc2 = 0ull;
    #pragma unroll 8
    for (int k = 0; k < 128; k++) {
        float hk = sh[wib][k];                              // LDS broadcast
        float2 wv = *(const float2*)&W2[k * 64 + c2];       // L1-resident
        acc2 = fma2(pk2(wv.x, wv.y), pk2(hk, hk), acc2);
    }
    float x0, x1;
    upk2(acc2, x0, x1);
    *(float2*)&g_xl2[dst * 64 + c2] = make_float2(x0, x1);

    float s2 = x0 * asv2[c2] + x1 * asv2[c2 + 1];
    float d2 = x0 * adv2[c2] + x1 * adv2[c2 + 1];
    #pragma unroll
    for (int ofs = 1; ofs < 32; ofs <<= 1) {
        s2 += __shfl_xor_sync(FULL, s2, ofs);
        d2 += __shfl_xor_sync(FULL, d2, ofs);
    }
    if (lane == 0) {
        g_as2[dst] = s2;
        g_ad2[dst] = d2;
    }
}

// ---------------- layer-2 aggregation (H=1, C=64): split halves, SINGLE PASS ----------
__global__ void __launch_bounds__(256) k_agg2(const float* __restrict__ b2,
                                              float* __restrict__ out) {
    int gw = (blockIdx.x * blockDim.x + threadIdx.x) >> 5;
    if (gw >= N_NODES) return;
    int lane = threadIdx.x & 31;
    int q4 = lane >> 2;            // quad-group 0..7: weight for edge sub+q4
    int half = lane >> 4;          // 0/1: which 4-edge subgroup to accumulate
    int col = (lane & 15) << 2;    // feature cols
    int dst = gw;
    int beg = g_off[dst], end = g_off[dst + 1];

    float adst = g_ad2[dst];
    float wself = __expf(lrelu(g_as2[dst] + adst));
    float denom = (lane < 4) ? wself : 0.f;   // once per bits-0..1 residue class
    unsigned long long a01 = 0ull, a23 = 0ull;
    if (half == 0) {
        float4 xv = *(const float4*)&g_xl2[dst * 64 + col];
        unsigned long long ws2 = pk2(wself, wself);
        a01 = fma2(pk2(xv.x, xv.y), ws2, 0ull);
        a23 = fma2(pk2(xv.z, xv.w), ws2, 0ull);
    }

    for (int base = beg; base < end; base += 32) {
        int mycsr = (base + lane < end) ? g_csr[base + lane] : 0;
        int n = min(32, end - base);
        for (int sub = 0; sub < n; sub += 8) {
            int eidx = sub + q4;
            int src_q = __shfl_sync(FULL, mycsr, eidx & 31);
            float e = lrelu(__ldg(&g_as2[src_q]) + adst);
            float w = (eidx < n) ? __expf(e) : 0.f;
            denom += w;   // identical within quad; xor-4/8/16 counts once
            int jbase = sub + (half << 2);
            #pragma unroll
            for (int jj = 0; jj < 4; jj++) {
                int j = jbase + jj;
                // unconditional shfls — all 32 lanes participate
                int srcj = __shfl_sync(FULL, mycsr, j & 31);
                float wj = __shfl_sync(FULL, w, ((j - sub) & 7) << 2);
                if (j < n) {
                    float4 v = *(const float4*)&g_xl2[srcj * 64 + col];
                    unsigned long long w2 = pk2(wj, wj);
                    a01 = fma2(pk2(v.x, v.y), w2, a01);
                    a23 = fma2(pk2(v.z, v.w), w2, a23);
                }
            }
        }
    }
    denom += __shfl_xor_sync(FULL, denom, 4);
    denom += __shfl_xor_sync(FULL, denom, 8);
    denom += __shfl_xor_sync(FULL, denom, 16);
    float invS = 1.f / (denom + 1e-16f);
    float ax, ay, az, aw;
    upk2(a01, ax, ay);
    upk2(a23, az, aw);
    ax += __shfl_xor_sync(FULL, ax, 16);
    ay += __shfl_xor_sync(FULL, ay, 16);
    az += __shfl_xor_sync(FULL, az, 16);
    aw += __shfl_xor_sync(FULL, aw, 16);

    if (lane < 16) {
        float4 o;
        o.x = ax * invS + b2[col + 0];
        o.y = ay * invS + b2[col + 1];
        o.z = az * invS + b2[col + 2];
        o.w = aw * invS + b2[col + 3];
        *(float4*)&out[dst * 64 + col] = o;
    }
}

// ---------------- launch: fork-join overlap of CSR build with GEMM1 ----------------
extern "C" void kernel_launch(void* const* d_in, const int* in_sizes, int n_in,
                              void* d_out, int out_size) {
    const float* x   = (const float*)d_in[0];
    const int*   ei  = (const int*)d_in[1];
    const float* W1  = (const float*)d_in[2];
    const float* as1 = (const float*)d_in[3];
    const float* ad1 = (const float*)d_in[4];
    const float* b1  = (const float*)d_in[5];
    const float* W2  = (const float*)d_in[6];
    const float* as2 = (const float*)d_in[7];
    const float* ad2 = (const float*)d_in[8];
    const float* b2  = (const float*)d_in[9];
    float* out = (float*)d_out;
    int E = in_sizes[1] / 2;
    int n4t = (E >> 2) + 1;  // int4 threads + 1 tail thread

    // One-time host-side resources (no device memory involved).
    static cudaStream_t s_csr = nullptr;
    static cudaEvent_t  ev_fork = nullptr, ev_join = nullptr;
    if (s_csr == nullptr) {
        cudaStreamCreateWithFlags(&s_csr, cudaStreamNonBlocking);
        cudaEventCreateWithFlags(&ev_fork, cudaEventDisableTiming);
        cudaEventCreateWithFlags(&ev_join, cudaEventDisableTiming);
    }

    cudaStream_t s0 = 0;  // capture-origin (default) stream

    // Fork: CSR build chain runs on s_csr, independent of gemm1att1.
    cudaEventRecord(ev_fork, s0);
    cudaStreamWaitEvent(s_csr, ev_fork, 0);
    k_zero<<<(N_NODES + 4 + 255) / 256, 256, 0, s_csr>>>();
    k_hist<<<(n4t + 255) / 256, 256, 0, s_csr>>>(ei, E);
    k_scan1<<<SCAN_B, 1024, 0, s_csr>>>();
    k_scan3<<<SCAN_B, 1024, 0, s_csr>>>();
    k_scatter<<<(n4t + 255) / 256, 256, 0, s_csr>>>(ei, E);
    cudaEventRecord(ev_join, s_csr);

    // Main chain on s0 (overlaps with CSR build).
    k_gemm1att1<<<N_NODES / 32, 128, 0, s0>>>(x, W1, as1, ad1);

    // Join: agg1f needs both xl1 (s0) and CSR (s_csr).
    cudaStreamWaitEvent(s0, ev_join, 0);
    k_agg1f<<<N_NODES / 8, 256, 0, s0>>>(b1, W2, as2, ad2);
    k_agg2<<<N_NODES / 8, 256, 0, s0>>>(b2, out);
}

// round 13
// speedup vs baseline: 1.0122x; 1.0122x over previous
#include <cuda_runtime.h>
#include <math.h>

#define N_NODES 100000
#define E_MAX   1600000
#define FULL    0xffffffffu
#define N4      (N_NODES / 4)        // 25000 int4 groups
#define SCAN_B  ((N4 + 1023) / 1024) // 25 scan blocks
#define SPLIT   49984                // pipeline split point (divisible by 8 and 32)

// ---------------- scratch (static __device__ — no dynamic alloc) ----------------
__device__ int   g_deg[N_NODES + 4];
__device__ int   g_off[N_NODES + 4];
__device__ int   g_cur[N_NODES + 4];
__device__ int   g_csr[E_MAX];
__device__ int   g_blk[SCAN_B];

__device__ float g_xl1[N_NODES * 128];  // x @ W1
__device__ float g_as1[N_NODES * 8];    // a_src layer1
__device__ float g_ad1[N_NODES * 8];    // a_dst layer1
__device__ float g_h  [N_NODES * 128];  // elu(gat1 out)
__device__ float g_xl2[N_NODES * 64];   // h @ W2
__device__ float g_as2[N_NODES];
__device__ float g_ad2[N_NODES];

__device__ __forceinline__ float lrelu(float x) { return x > 0.f ? x : 0.2f * x; }
__device__ __forceinline__ float elu_f(float x) { return x > 0.f ? x : expm1f(x); }

// packed f32x2 helpers (FFMA2 — PTX-only, doubles fp32 FMA throughput on sm_103a)
__device__ __forceinline__ unsigned long long pk2(float lo, float hi) {
    unsigned long long r;
    asm("mov.b64 %0, {%1, %2};" : "=l"(r) : "f"(lo), "f"(hi));
    return r;
}
__device__ __forceinline__ void upk2(unsigned long long v, float& lo, float& hi) {
    asm("mov.b64 {%0, %1}, %2;" : "=f"(lo), "=f"(hi) : "l"(v));
}
__device__ __forceinline__ unsigned long long fma2(unsigned long long a,
                                                   unsigned long long b,
                                                   unsigned long long c) {
    unsigned long long d;
    asm("fma.rn.f32x2 %0, %1, %2, %3;" : "=l"(d) : "l"(a), "l"(b), "l"(c));
    return d;
}

// ---------------- CSR build ----------------
__global__ void k_zero() {
    int i = blockIdx.x * blockDim.x + threadIdx.x;
    if (i < N_NODES + 4) g_deg[i] = 0;
}

__global__ void k_hist(const int* __restrict__ ei, int E) {
    int t = blockIdx.x * blockDim.x + threadIdx.x;
    int n4 = E >> 2;
    const int4* d4 = (const int4*)(ei + E);
    if (t < n4) {
        int4 v = d4[t];
        atomicAdd(&g_deg[v.x], 1);
        atomicAdd(&g_deg[v.y], 1);
        atomicAdd(&g_deg[v.z], 1);
        atomicAdd(&g_deg[v.w], 1);
    } else if (t == n4) {
        for (int e = n4 * 4; e < E; e++) atomicAdd(&g_deg[ei[E + e]], 1);
    }
}

// ---- multi-block scan: phase 1 — per-block exclusive scan + block totals ----
__global__ void __launch_bounds__(1024) k_scan1() {
    __shared__ int warp_sums[32];
    int tid = threadIdx.x, lane = tid & 31, wid = tid >> 5;
    int i = blockIdx.x * 1024 + tid;
    const int4* deg4 = (const int4*)g_deg;
    int4* off4 = (int4*)g_off;

    int4 v = (i < N4) ? deg4[i] : make_int4(0, 0, 0, 0);
    int tot = v.x + v.y + v.z + v.w;
    int xs = tot;
    #pragma unroll
    for (int o = 1; o < 32; o <<= 1) {
        int t = __shfl_up_sync(FULL, xs, o);
        if (lane >= o) xs += t;
    }
    if (lane == 31) warp_sums[wid] = xs;
    __syncthreads();
    if (wid == 0) {
        int ws = warp_sums[lane];
        #pragma unroll
        for (int o = 1; o < 32; o <<= 1) {
            int t = __shfl_up_sync(FULL, ws, o);
            if (lane >= o) ws += t;
        }
        warp_sums[lane] = ws;
    }
    __syncthreads();
    int incl = xs + (wid > 0 ? warp_sums[wid - 1] : 0);
    int b0 = incl - tot;
    if (i < N4) {
        int4 o;
        o.x = b0;
        o.y = b0 + v.x;
        o.z = o.y + v.y;
        o.w = o.z + v.z;
        off4[i] = o;
    }
    if (tid == 0) g_blk[blockIdx.x] = warp_sums[31];
}

// ---- scan phase 2+3 merged ----
__global__ void __launch_bounds__(1024) k_scan3() {
    __shared__ int s_off[32];
    int tid = threadIdx.x;
    if (tid < 32) {
        int t = (tid < SCAN_B) ? g_blk[tid] : 0;
        int xs = t;
        #pragma unroll
        for (int o = 1; o < 32; o <<= 1) {
            int u = __shfl_up_sync(FULL, xs, o);
            if (tid >= o) xs += u;
        }
        s_off[tid] = xs - t;
        if (blockIdx.x == 0 && tid == 31) g_off[N_NODES] = xs;
    }
    __syncthreads();
    int i = blockIdx.x * 1024 + tid;
    if (i < N4) {
        int add = s_off[blockIdx.x];
        int4* off4 = (int4*)g_off;
        int4* cur4 = (int4*)g_cur;
        int4 o = off4[i];
        o.x += add; o.y += add; o.z += add; o.w += add;
        off4[i] = o;
        cur4[i] = o;
    }
}

__global__ void k_scatter(const int* __restrict__ ei, int E) {
    int t = blockIdx.x * blockDim.x + threadIdx.x;
    int n4 = E >> 2;
    const int4* s4 = (const int4*)ei;
    const int4* d4 = (const int4*)(ei + E);
    if (t < n4) {
        int4 s = s4[t];
        int4 d = d4[t];
        g_csr[atomicAdd(&g_cur[d.x], 1)] = s.x;
        g_csr[atomicAdd(&g_cur[d.y], 1)] = s.y;
        g_csr[atomicAdd(&g_cur[d.z], 1)] = s.z;
        g_csr[atomicAdd(&g_cur[d.w], 1)] = s.w;
    } else if (t == n4) {
        for (int e = n4 * 4; e < E; e++)
            g_csr[atomicAdd(&g_cur[ei[E + e]], 1)] = ei[e];
    }
}

// ---------------- GEMM1 + att1 fused ----------------
__global__ void __launch_bounds__(128) k_gemm1att1(const float* __restrict__ x,
                                                   const float* __restrict__ W,
                                                   const float* __restrict__ asv,
                                                   const float* __restrict__ adv) {
    __shared__ __align__(16) float sxT[128][36];
    int c = threadIdx.x;
    int row0 = blockIdx.x * 32;
    #pragma unroll 8
    for (int r = 0; r < 32; r++)
        sxT[c][r] = x[(row0 + r) * 128 + c];
    __syncthreads();

    unsigned long long acc[16];
    #pragma unroll
    for (int i = 0; i < 16; i++) acc[i] = 0ull;

    #pragma unroll 4
    for (int k = 0; k < 128; k++) {
        float w = W[k * 128 + c];
        unsigned long long w2 = pk2(w, w);
        const float4* col4 = (const float4*)&sxT[k][0];
        #pragma unroll
        for (int i = 0; i < 8; i++) {
            float4 a = col4[i];
            acc[2 * i]     = fma2(pk2(a.x, a.y), w2, acc[2 * i]);
            acc[2 * i + 1] = fma2(pk2(a.z, a.w), w2, acc[2 * i + 1]);
        }
    }

    float as_c = asv[c], ad_c = adv[c];
    int head = c >> 4, l16 = c & 15;
    #pragma unroll
    for (int i = 0; i < 16; i++) {
        float o0, o1;
        upk2(acc[i], o0, o1);
        g_xl1[(row0 + 2 * i) * 128 + c] = o0;
        g_xl1[(row0 + 2 * i + 1) * 128 + c] = o1;
        float s0 = o0 * as_c, d0 = o0 * ad_c;
        float s1 = o1 * as_c, d1 = o1 * ad_c;
        #pragma unroll
        for (int ofs = 1; ofs < 16; ofs <<= 1) {
            s0 += __shfl_xor_sync(FULL, s0, ofs);
            d0 += __shfl_xor_sync(FULL, d0, ofs);
            s1 += __shfl_xor_sync(FULL, s1, ofs);
            d1 += __shfl_xor_sync(FULL, d1, ofs);
        }
        if (l16 == 0) {
            g_as1[(row0 + 2 * i) * 8 + head] = s0;
            g_ad1[(row0 + 2 * i) * 8 + head] = d0;
            g_as1[(row0 + 2 * i + 1) * 8 + head] = s1;
            g_ad1[(row0 + 2 * i + 1) * 8 + head] = d1;
        }
    }
}

// ---------------- GEMM2 + att2 fused (row-range version) ----------------
__global__ void __launch_bounds__(64) k_gemm2att2(const float* __restrict__ W,
                                                  const float* __restrict__ asv,
                                                  const float* __restrict__ adv,
                                                  int row_base) {
    __shared__ __align__(16) float shT[128][36];
    __shared__ float red[2][32][2];
    int c = threadIdx.x;  // 0..63
    int row0 = row_base + blockIdx.x * 32;
    int k0 = c, k1 = c + 64;
    #pragma unroll 4
    for (int r = 0; r < 32; r++) {
        shT[k0][r] = g_h[(row0 + r) * 128 + k0];
        shT[k1][r] = g_h[(row0 + r) * 128 + k1];
    }
    __syncthreads();

    unsigned long long acc[16];
    #pragma unroll
    for (int i = 0; i < 16; i++) acc[i] = 0ull;

    #pragma unroll 4
    for (int k = 0; k < 128; k++) {
        float w = W[k * 64 + c];
        unsigned long long w2 = pk2(w, w);
        const float4* col4 = (const float4*)&shT[k][0];
        #pragma unroll
        for (int i = 0; i < 8; i++) {
            float4 a = col4[i];
            acc[2 * i]     = fma2(pk2(a.x, a.y), w2, acc[2 * i]);
            acc[2 * i + 1] = fma2(pk2(a.z, a.w), w2, acc[2 * i + 1]);
        }
    }

    float as_c = asv[c], ad_c = adv[c];
    int lane = c & 31, wrp = c >> 5;
    #pragma unroll
    for (int i = 0; i < 16; i++) {
        float o0, o1;
        upk2(acc[i], o0, o1);
        g_xl2[(row0 + 2 * i) * 64 + c] = o0;
        g_xl2[(row0 + 2 * i + 1) * 64 + c] = o1;
        float s0 = o0 * as_c, d0 = o0 * ad_c;
        float s1 = o1 * as_c, d1 = o1 * ad_c;
        #pragma unroll
        for (int ofs = 1; ofs < 32; ofs <<= 1) {
            s0 += __shfl_xor_sync(FULL, s0, ofs);
            d0 += __shfl_xor_sync(FULL, d0, ofs);
            s1 += __shfl_xor_sync(FULL, s1, ofs);
            d1 += __shfl_xor_sync(FULL, d1, ofs);
        }
        if (lane == 0) {
            red[wrp][2 * i][0] = s0;
            red[wrp][2 * i][1] = d0;
            red[wrp][2 * i + 1][0] = s1;
            red[wrp][2 * i + 1][1] = d1;
        }
    }
    __syncthreads();
    if (c < 32) {
        g_as2[row0 + c] = red[0][c][0] + red[1][c][0];
        g_ad2[row0 + c] = red[0][c][1] + red[1][c][1];
    }
}

// ---------------- layer-1 aggregation (node-range version) ----------------
__global__ void __launch_bounds__(256) k_agg1(const float* __restrict__ b1,
                                              int node0, int node1) {
    int gw = node0 + ((blockIdx.x * blockDim.x + threadIdx.x) >> 5);
    if (gw >= node1) return;
    int lane = threadIdx.x & 31;
    int dst = gw;
    int beg = g_off[dst], end = g_off[dst + 1];
    int h = lane & 7, g = lane >> 3;
    int col = lane << 2, hs = lane >> 2;

    float adst = g_ad1[dst * 8 + h];
    float wself = __expf(lrelu(g_as1[dst * 8 + h] + adst));
    float denom = (g == 0) ? wself : 0.f;   // once per 8-lane residue class
    float wself_sel = __shfl_sync(FULL, wself, hs);
    float4 xv = *(const float4*)&g_xl1[dst * 128 + col];
    unsigned long long ws2 = pk2(wself_sel, wself_sel);
    unsigned long long a01 = fma2(pk2(xv.x, xv.y), ws2, 0ull);
    unsigned long long a23 = fma2(pk2(xv.z, xv.w), ws2, 0ull);

    for (int base = beg; base < end; base += 32) {
        int mycsr = (base + lane < end) ? g_csr[base + lane] : 0;
        int n = min(32, end - base);
        for (int sub = 0; sub < n; sub += 4) {
            int src_g = __shfl_sync(FULL, mycsr, sub + g);
            float e = lrelu(__ldg(&g_as1[src_g * 8 + h]) + adst);
            float w = ((sub + g) < n) ? __expf(e) : 0.f;
            denom += w;   // identical within 8-lane group; xor-8/16 tree counts once
            #pragma unroll
            for (int j = 0; j < 4; j++) {
                if (sub + j < n) {   // warp-uniform condition
                    int srcj = __shfl_sync(FULL, mycsr, sub + j);
                    float wsel = __shfl_sync(FULL, w, (j << 3) + hs);
                    float4 v = *(const float4*)&g_xl1[srcj * 128 + col];
                    unsigned long long w2 = pk2(wsel, wsel);
                    a01 = fma2(pk2(v.x, v.y), w2, a01);
                    a23 = fma2(pk2(v.z, v.w), w2, a23);
                }
            }
        }
    }
    denom += __shfl_xor_sync(FULL, denom, 8);
    denom += __shfl_xor_sync(FULL, denom, 16);
    float invS = 1.f / (denom + 1e-16f);
    float invS_sel = __shfl_sync(FULL, invS, hs);

    float ax, ay, az, aw;
    upk2(a01, ax, ay);
    upk2(a23, az, aw);
    float4 o;
    o.x = elu_f(ax * invS_sel + b1[col + 0]);
    o.y = elu_f(ay * invS_sel + b1[col + 1]);
    o.z = elu_f(az * invS_sel + b1[col + 2]);
    o.w = elu_f(aw * invS_sel + b1[col + 3]);
    *(float4*)&g_h[dst * 128 + col] = o;
}

// ---------------- layer-2 aggregation (H=1, C=64): split halves, SINGLE PASS ----------
__global__ void __launch_bounds__(256) k_agg2(const float* __restrict__ b2,
                                              float* __restrict__ out) {
    int gw = (blockIdx.x * blockDim.x + threadIdx.x) >> 5;
    if (gw >= N_NODES) return;
    int lane = threadIdx.x & 31;
    int q4 = lane >> 2;            // quad-group 0..7: weight for edge sub+q4
    int half = lane >> 4;          // 0/1: which 4-edge subgroup to accumulate
    int col = (lane & 15) << 2;    // feature cols
    int dst = gw;
    int beg = g_off[dst], end = g_off[dst + 1];

    float adst = g_ad2[dst];
    float wself = __expf(lrelu(g_as2[dst] + adst));
    float denom = (lane < 4) ? wself : 0.f;   // once per bits-0..1 residue class
    unsigned long long a01 = 0ull, a23 = 0ull;
    if (half == 0) {
        float4 xv = *(const float4*)&g_xl2[dst * 64 + col];
        unsigned long long ws2 = pk2(wself, wself);
        a01 = fma2(pk2(xv.x, xv.y), ws2, 0ull);
        a23 = fma2(pk2(xv.z, xv.w), ws2, 0ull);
    }

    for (int base = beg; base < end; base += 32) {
        int mycsr = (base + lane < end) ? g_csr[base + lane] : 0;
        int n = min(32, end - base);
        for (int sub = 0; sub < n; sub += 8) {
            int eidx = sub + q4;
            int src_q = __shfl_sync(FULL, mycsr, eidx & 31);
            float e = lrelu(__ldg(&g_as2[src_q]) + adst);
            float w = (eidx < n) ? __expf(e) : 0.f;
            denom += w;   // identical within quad; xor-4/8/16 counts once
            int jbase = sub + (half << 2);
            #pragma unroll
            for (int jj = 0; jj < 4; jj++) {
                int j = jbase + jj;
                // unconditional shfls — all 32 lanes participate
                int srcj = __shfl_sync(FULL, mycsr, j & 31);
                float wj = __shfl_sync(FULL, w, ((j - sub) & 7) << 2);
                if (j < n) {
                    float4 v = *(const float4*)&g_xl2[srcj * 64 + col];
                    unsigned long long w2 = pk2(wj, wj);
                    a01 = fma2(pk2(v.x, v.y), w2, a01);
                    a23 = fma2(pk2(v.z, v.w), w2, a23);
                }
            }
        }
    }
    denom += __shfl_xor_sync(FULL, denom, 4);
    denom += __shfl_xor_sync(FULL, denom, 8);
    denom += __shfl_xor_sync(FULL, denom, 16);
    float invS = 1.f / (denom + 1e-16f);
    float ax, ay, az, aw;
    upk2(a01, ax, ay);
    upk2(a23, az, aw);
    ax += __shfl_xor_sync(FULL, ax, 16);
    ay += __shfl_xor_sync(FULL, ay, 16);
    az += __shfl_xor_sync(FULL, az, 16);
    aw += __shfl_xor_sync(FULL, aw, 16);

    if (lane < 16) {
        float4 o;
        o.x = ax * invS + b2[col + 0];
        o.y = ay * invS + b2[col + 1];
        o.z = az * invS + b2[col + 2];
        o.w = aw * invS + b2[col + 3];
        *(float4*)&out[dst * 64 + col] = o;
    }
}

// ---------------- launch: fork-join + agg1/gemm2 pipeline ----------------
extern "C" void kernel_launch(void* const* d_in, const int* in_sizes, int n_in,
                              void* d_out, int out_size) {
    const float* x   = (const float*)d_in[0];
    const int*   ei  = (const int*)d_in[1];
    const float* W1  = (const float*)d_in[2];
    const float* as1 = (const float*)d_in[3];
    const float* ad1 = (const float*)d_in[4];
    const float* b1  = (const float*)d_in[5];
    const float* W2  = (const float*)d_in[6];
    const float* as2 = (const float*)d_in[7];
    const float* ad2 = (const float*)d_in[8];
    const float* b2  = (const float*)d_in[9];
    float* out = (float*)d_out;
    int E = in_sizes[1] / 2;
    int n4t = (E >> 2) + 1;  // int4 threads + 1 tail thread

    // One-time host-side resources (no device memory involved).
    static cudaStream_t s_aux = nullptr;
    static cudaEvent_t  ev_fork = nullptr, ev_join = nullptr, ev_a = nullptr, ev_g = nullptr;
    if (s_aux == nullptr) {
        cudaStreamCreateWithFlags(&s_aux, cudaStreamNonBlocking);
        cudaEventCreateWithFlags(&ev_fork, cudaEventDisableTiming);
        cudaEventCreateWithFlags(&ev_join, cudaEventDisableTiming);
        cudaEventCreateWithFlags(&ev_a, cudaEventDisableTiming);
        cudaEventCreateWithFlags(&ev_g, cudaEventDisableTiming);
    }

    cudaStream_t s0 = 0;  // capture-origin (default) stream

    // Fork: CSR build chain runs on s_aux, independent of gemm1att1.
    cudaEventRecord(ev_fork, s0);
    cudaStreamWaitEvent(s_aux, ev_fork, 0);
    k_zero<<<(N_NODES + 4 + 255) / 256, 256, 0, s_aux>>>();
    k_hist<<<(n4t + 255) / 256, 256, 0, s_aux>>>(ei, E);
    k_scan1<<<SCAN_B, 1024, 0, s_aux>>>();
    k_scan3<<<SCAN_B, 1024, 0, s_aux>>>();
    k_scatter<<<(n4t + 255) / 256, 256, 0, s_aux>>>(ei, E);
    cudaEventRecord(ev_join, s_aux);

    // Main chain on s0 (overlaps with CSR build).
    k_gemm1att1<<<N_NODES / 32, 128, 0, s0>>>(x, W1, as1, ad1);

    // Join: agg1 needs both xl1 (s0) and CSR (s_aux).
    cudaStreamWaitEvent(s0, ev_join, 0);

    // Pipeline: agg1_a -> (agg1_b || gemm2_a) -> gemm2_b -> agg2
    k_agg1<<<SPLIT / 8, 256, 0, s0>>>(b1, 0, SPLIT);
    cudaEventRecord(ev_a, s0);
    cudaStreamWaitEvent(s_aux, ev_a, 0);
    k_gemm2att2<<<SPLIT / 32, 64, 0, s_aux>>>(W2, as2, ad2, 0);
    cudaEventRecord(ev_g, s_aux);

    k_agg1<<<(N_NODES - SPLIT) / 8, 256, 0, s0>>>(b1, SPLIT, N_NODES);
    cudaStreamWaitEvent(s0, ev_g, 0);
    k_gemm2att2<<<(N_NODES - SPLIT) / 32, 64, 0, s0>>>(W2, as2, ad2, SPLIT);
    k_agg2<<<N_NODES / 8, 256, 0, s0>>>(b2, out);
}

// round 14
// speedup vs baseline: 1.0542x; 1.0415x over previous
#include <cuda_runtime.h>
#include <math.h>

#define N_NODES 100000
#define E_MAX   1600000
#define FULL    0xffffffffu
#define N4      (N_NODES / 4)        // 25000 int4 groups
#define SCAN_B  ((N4 + 1023) / 1024) // 25 scan blocks
#define PUB_FLAG (1 << 30)

// ---------------- scratch (static __device__ — no dynamic alloc) ----------------
__device__ int   g_deg[N_NODES + 4];
__device__ int   g_off[N_NODES + 4];
__device__ int   g_cur[N_NODES + 4];
__device__ int   g_csr[E_MAX];
__device__ int   g_pub[SCAN_B];      // decoupled-lookback publish slots (memset to 0)

__device__ float g_xl1[N_NODES * 128];  // x @ W1
__device__ float g_as1[N_NODES * 8];    // a_src layer1
__device__ float g_ad1[N_NODES * 8];    // a_dst layer1
__device__ float g_h  [N_NODES * 128];  // elu(gat1 out)
__device__ float g_xl2[N_NODES * 64];   // h @ W2
__device__ float g_as2[N_NODES];
__device__ float g_ad2[N_NODES];

__device__ __forceinline__ float lrelu(float x) { return x > 0.f ? x : 0.2f * x; }
__device__ __forceinline__ float elu_f(float x) { return x > 0.f ? x : expm1f(x); }

// packed f32x2 helpers (FFMA2 — PTX-only, doubles fp32 FMA throughput on sm_103a)
__device__ __forceinline__ unsigned long long pk2(float lo, float hi) {
    unsigned long long r;
    asm("mov.b64 %0, {%1, %2};" : "=l"(r) : "f"(lo), "f"(hi));
    return r;
}
__device__ __forceinline__ void upk2(unsigned long long v, float& lo, float& hi) {
    asm("mov.b64 {%0, %1}, %2;" : "=f"(lo), "=f"(hi) : "l"(v));
}
__device__ __forceinline__ unsigned long long fma2(unsigned long long a,
                                                   unsigned long long b,
                                                   unsigned long long c) {
    unsigned long long d;
    asm("fma.rn.f32x2 %0, %1, %2, %3;" : "=l"(d) : "l"(a), "l"(b), "l"(c));
    return d;
}

// ---------------- CSR build ----------------
__global__ void k_hist(const int* __restrict__ ei, int E) {
    int t = blockIdx.x * blockDim.x + threadIdx.x;
    int n4 = E >> 2;
    const int4* d4 = (const int4*)(ei + E);
    if (t < n4) {
        int4 v = d4[t];
        atomicAdd(&g_deg[v.x], 1);
        atomicAdd(&g_deg[v.y], 1);
        atomicAdd(&g_deg[v.z], 1);
        atomicAdd(&g_deg[v.w], 1);
    } else if (t == n4) {
        for (int e = n4 * 4; e < E; e++) atomicAdd(&g_deg[ei[E + e]], 1);
    }
}

// ---- single-kernel scan with decoupled lookback (25 co-resident blocks) ----
__global__ void __launch_bounds__(1024) k_scan_lb() {
    __shared__ int warp_sums[32];
    __shared__ int s_carry;
    int tid = threadIdx.x, lane = tid & 31, wid = tid >> 5;
    int b = blockIdx.x;
    int i = b * 1024 + tid;
    const int4* deg4 = (const int4*)g_deg;
    int4* off4 = (int4*)g_off;
    int4* cur4 = (int4*)g_cur;

    int4 v = (i < N4) ? deg4[i] : make_int4(0, 0, 0, 0);
    int tot = v.x + v.y + v.z + v.w;
    int xs = tot;
    #pragma unroll
    for (int o = 1; o < 32; o <<= 1) {
        int t = __shfl_up_sync(FULL, xs, o);
        if (lane >= o) xs += t;
    }
    if (lane == 31) warp_sums[wid] = xs;
    __syncthreads();
    if (wid == 0) {
        int ws = warp_sums[lane];
        #pragma unroll
        for (int o = 1; o < 32; o <<= 1) {
            int t = __shfl_up_sync(FULL, ws, o);
            if (lane >= o) ws += t;
        }
        warp_sums[lane] = ws;
    }
    __syncthreads();

    // publish this block's total, then lookback over predecessors (warp 0)
    if (tid == 0) atomicExch(&g_pub[b], warp_sums[31] + PUB_FLAG);
    if (wid == 0) {
        int sum = 0;
        if (lane < b) {
            int val;
            do { val = atomicAdd(&g_pub[lane], 0); } while (val < PUB_FLAG);
            sum = val - PUB_FLAG;
        }
        #pragma unroll
        for (int o = 16; o > 0; o >>= 1) sum += __shfl_xor_sync(FULL, sum, o);
        if (lane == 0) s_carry = sum;
    }
    __syncthreads();

    int carry = s_carry;
    int incl = xs + (wid > 0 ? warp_sums[wid - 1] : 0);
    int b0 = carry + incl - tot;
    if (i < N4) {
        int4 o;
        o.x = b0;
        o.y = b0 + v.x;
        o.z = o.y + v.y;
        o.w = o.z + v.z;
        off4[i] = o;
        cur4[i] = o;
    }
    if (b == SCAN_B - 1 && tid == 0) g_off[N_NODES] = carry + warp_sums[31];
}

__global__ void k_scatter(const int* __restrict__ ei, int E) {
    int t = blockIdx.x * blockDim.x + threadIdx.x;
    int n4 = E >> 2;
    const int4* s4 = (const int4*)ei;
    const int4* d4 = (const int4*)(ei + E);
    if (t < n4) {
        int4 s = s4[t];
        int4 d = d4[t];
        g_csr[atomicAdd(&g_cur[d.x], 1)] = s.x;
        g_csr[atomicAdd(&g_cur[d.y], 1)] = s.y;
        g_csr[atomicAdd(&g_cur[d.z], 1)] = s.z;
        g_csr[atomicAdd(&g_cur[d.w], 1)] = s.w;
    } else if (t == n4) {
        for (int e = n4 * 4; e < E; e++)
            g_csr[atomicAdd(&g_cur[ei[E + e]], 1)] = ei[e];
    }
}

// ---------------- GEMM1 + att1 fused ----------------
__global__ void __launch_bounds__(128) k_gemm1att1(const float* __restrict__ x,
                                                   const float* __restrict__ W,
                                                   const float* __restrict__ asv,
                                                   const float* __restrict__ adv) {
    __shared__ __align__(16) float sxT[128][36];
    int c = threadIdx.x;
    int row0 = blockIdx.x * 32;
    #pragma unroll 8
    for (int r = 0; r < 32; r++)
        sxT[c][r] = x[(row0 + r) * 128 + c];
    __syncthreads();

    unsigned long long acc[16];
    #pragma unroll
    for (int i = 0; i < 16; i++) acc[i] = 0ull;

    #pragma unroll 4
    for (int k = 0; k < 128; k++) {
        float w = W[k * 128 + c];
        unsigned long long w2 = pk2(w, w);
        const float4* col4 = (const float4*)&sxT[k][0];
        #pragma unroll
        for (int i = 0; i < 8; i++) {
            float4 a = col4[i];
            acc[2 * i]     = fma2(pk2(a.x, a.y), w2, acc[2 * i]);
            acc[2 * i + 1] = fma2(pk2(a.z, a.w), w2, acc[2 * i + 1]);
        }
    }

    float as_c = asv[c], ad_c = adv[c];
    int head = c >> 4, l16 = c & 15;
    #pragma unroll
    for (int i = 0; i < 16; i++) {
        float o0, o1;
        upk2(acc[i], o0, o1);
        g_xl1[(row0 + 2 * i) * 128 + c] = o0;
        g_xl1[(row0 + 2 * i + 1) * 128 + c] = o1;
        float s0 = o0 * as_c, d0 = o0 * ad_c;
        float s1 = o1 * as_c, d1 = o1 * ad_c;
        #pragma unroll
        for (int ofs = 1; ofs < 16; ofs <<= 1) {
            s0 += __shfl_xor_sync(FULL, s0, ofs);
            d0 += __shfl_xor_sync(FULL, d0, ofs);
            s1 += __shfl_xor_sync(FULL, s1, ofs);
            d1 += __shfl_xor_sync(FULL, d1, ofs);
        }
        if (l16 == 0) {
            g_as1[(row0 + 2 * i) * 8 + head] = s0;
            g_ad1[(row0 + 2 * i) * 8 + head] = d0;
            g_as1[(row0 + 2 * i + 1) * 8 + head] = s1;
            g_ad1[(row0 + 2 * i + 1) * 8 + head] = d1;
        }
    }
}

// ---------------- GEMM2 + att2 fused ----------------
__global__ void __launch_bounds__(64) k_gemm2att2(const float* __restrict__ W,
                                                  const float* __restrict__ asv,
                                                  const float* __restrict__ adv) {
    __shared__ __align__(16) float shT[128][36];
    __shared__ float red[2][32][2];
    int c = threadIdx.x;  // 0..63
    int row0 = blockIdx.x * 32;
    int k0 = c, k1 = c + 64;
    #pragma unroll 4
    for (int r = 0; r < 32; r++) {
        shT[k0][r] = g_h[(row0 + r) * 128 + k0];
        shT[k1][r] = g_h[(row0 + r) * 128 + k1];
    }
    __syncthreads();

    unsigned long long acc[16];
    #pragma unroll
    for (int i = 0; i < 16; i++) acc[i] = 0ull;

    #pragma unroll 4
    for (int k = 0; k < 128; k++) {
        float w = W[k * 64 + c];
        unsigned long long w2 = pk2(w, w);
        const float4* col4 = (const float4*)&shT[k][0];
        #pragma unroll
        for (int i = 0; i < 8; i++) {
            float4 a = col4[i];
            acc[2 * i]     = fma2(pk2(a.x, a.y), w2, acc[2 * i]);
            acc[2 * i + 1] = fma2(pk2(a.z, a.w), w2, acc[2 * i + 1]);
        }
    }

    float as_c = asv[c], ad_c = adv[c];
    int lane = c & 31, wrp = c >> 5;
    #pragma unroll
    for (int i = 0; i < 16; i++) {
        float o0, o1;
        upk2(acc[i], o0, o1);
        g_xl2[(row0 + 2 * i) * 64 + c] = o0;
        g_xl2[(row0 + 2 * i + 1) * 64 + c] = o1;
        float s0 = o0 * as_c, d0 = o0 * ad_c;
        float s1 = o1 * as_c, d1 = o1 * ad_c;
        #pragma unroll
        for (int ofs = 1; ofs < 32; ofs <<= 1) {
            s0 += __shfl_xor_sync(FULL, s0, ofs);
            d0 += __shfl_xor_sync(FULL, d0, ofs);
            s1 += __shfl_xor_sync(FULL, s1, ofs);
            d1 += __shfl_xor_sync(FULL, d1, ofs);
        }
        if (lane == 0) {
            red[wrp][2 * i][0] = s0;
            red[wrp][2 * i][1] = d0;
            red[wrp][2 * i + 1][0] = s1;
            red[wrp][2 * i + 1][1] = d1;
        }
    }
    __syncthreads();
    if (c < 32) {
        g_as2[row0 + c] = red[0][c][0] + red[1][c][0];
        g_ad2[row0 + c] = red[0][c][1] + red[1][c][1];
    }
}

// ---------------- layer-1 aggregation: one warp per node, SINGLE PASS ----------------
__global__ void __launch_bounds__(256) k_agg1(const float* __restrict__ b1) {
    int gw = (blockIdx.x * blockDim.x + threadIdx.x) >> 5;
    if (gw >= N_NODES) return;
    int lane = threadIdx.x & 31;
    int dst = gw;
    int beg = g_off[dst], end = g_off[dst + 1];
    int h = lane & 7, g = lane >> 3;
    int col = lane << 2, hs = lane >> 2;

    float adst = g_ad1[dst * 8 + h];
    float wself = __expf(lrelu(g_as1[dst * 8 + h] + adst));
    float denom = (g == 0) ? wself : 0.f;   // once per 8-lane residue class
    float wself_sel = __shfl_sync(FULL, wself, hs);
    float4 xv = *(const float4*)&g_xl1[dst * 128 + col];
    unsigned long long ws2 = pk2(wself_sel, wself_sel);
    unsigned long long a01 = fma2(pk2(xv.x, xv.y), ws2, 0ull);
    unsigned long long a23 = fma2(pk2(xv.z, xv.w), ws2, 0ull);

    for (int base = beg; base < end; base += 32) {
        int mycsr = (base + lane < end) ? g_csr[base + lane] : 0;
        int n = min(32, end - base);
        for (int sub = 0; sub < n; sub += 4) {
            int src_g = __shfl_sync(FULL, mycsr, sub + g);
            float e = lrelu(__ldg(&g_as1[src_g * 8 + h]) + adst);
            float w = ((sub + g) < n) ? __expf(e) : 0.f;
            denom += w;   // identical within 8-lane group; xor-8/16 tree counts once
            #pragma unroll
            for (int j = 0; j < 4; j++) {
                if (sub + j < n) {   // warp-uniform condition
                    int srcj = __shfl_sync(FULL, mycsr, sub + j);
                    float wsel = __shfl_sync(FULL, w, (j << 3) + hs);
                    float4 v = *(const float4*)&g_xl1[srcj * 128 + col];
                    unsigned long long w2 = pk2(wsel, wsel);
                    a01 = fma2(pk2(v.x, v.y), w2, a01);
                    a23 = fma2(pk2(v.z, v.w), w2, a23);
                }
            }
        }
    }
    denom += __shfl_xor_sync(FULL, denom, 8);
    denom += __shfl_xor_sync(FULL, denom, 16);
    float invS = 1.f / (denom + 1e-16f);
    float invS_sel = __shfl_sync(FULL, invS, hs);

    float ax, ay, az, aw;
    upk2(a01, ax, ay);
    upk2(a23, az, aw);
    float4 o;
    o.x = elu_f(ax * invS_sel + b1[col + 0]);
    o.y = elu_f(ay * invS_sel + b1[col + 1]);
    o.z = elu_f(az * invS_sel + b1[col + 2]);
    o.w = elu_f(aw * invS_sel + b1[col + 3]);
    *(float4*)&g_h[dst * 128 + col] = o;
}

// ---------------- layer-2 aggregation (H=1, C=64): split halves, SINGLE PASS ----------
__global__ void __launch_bounds__(256) k_agg2(const float* __restrict__ b2,
                                              float* __restrict__ out) {
    int gw = (blockIdx.x * blockDim.x + threadIdx.x) >> 5;
    if (gw >= N_NODES) return;
    int lane = threadIdx.x & 31;
    int q4 = lane >> 2;            // quad-group 0..7: weight for edge sub+q4
    int half = lane >> 4;          // 0/1: which 4-edge subgroup to accumulate
    int col = (lane & 15) << 2;    // feature cols
    int dst = gw;
    int beg = g_off[dst], end = g_off[dst + 1];

    float adst = g_ad2[dst];
    float wself = __expf(lrelu(g_as2[dst] + adst));
    float denom = (lane < 4) ? wself : 0.f;   // once per bits-0..1 residue class
    unsigned long long a01 = 0ull, a23 = 0ull;
    if (half == 0) {
        float4 xv = *(const float4*)&g_xl2[dst * 64 + col];
        unsigned long long ws2 = pk2(wself, wself);
        a01 = fma2(pk2(xv.x, xv.y), ws2, 0ull);
        a23 = fma2(pk2(xv.z, xv.w), ws2, 0ull);
    }

    for (int base = beg; base < end; base += 32) {
        int mycsr = (base + lane < end) ? g_csr[base + lane] : 0;
        int n = min(32, end - base);
        for (int sub = 0; sub < n; sub += 8) {
            int eidx = sub + q4;
            int src_q = __shfl_sync(FULL, mycsr, eidx & 31);
            float e = lrelu(__ldg(&g_as2[src_q]) + adst);
            float w = (eidx < n) ? __expf(e) : 0.f;
            denom += w;   // identical within quad; xor-4/8/16 counts once
            int jbase = sub + (half << 2);
            #pragma unroll
            for (int jj = 0; jj < 4; jj++) {
                int j = jbase + jj;
                // unconditional shfls — all 32 lanes participate
                int srcj = __shfl_sync(FULL, mycsr, j & 31);
                float wj = __shfl_sync(FULL, w, ((j - sub) & 7) << 2);
                if (j < n) {
                    float4 v = *(const float4*)&g_xl2[srcj * 64 + col];
                    unsigned long long w2 = pk2(wj, wj);
                    a01 = fma2(pk2(v.x, v.y), w2, a01);
                    a23 = fma2(pk2(v.z, v.w), w2, a23);
                }
            }
        }
    }
    denom += __shfl_xor_sync(FULL, denom, 4);
    denom += __shfl_xor_sync(FULL, denom, 8);
    denom += __shfl_xor_sync(FULL, denom, 16);
    float invS = 1.f / (denom + 1e-16f);
    float ax, ay, az, aw;
    upk2(a01, ax, ay);
    upk2(a23, az, aw);
    ax += __shfl_xor_sync(FULL, ax, 16);
    ay += __shfl_xor_sync(FULL, ay, 16);
    az += __shfl_xor_sync(FULL, az, 16);
    aw += __shfl_xor_sync(FULL, aw, 16);

    if (lane < 16) {
        float4 o;
        o.x = ax * invS + b2[col + 0];
        o.y = ay * invS + b2[col + 1];
        o.z = az * invS + b2[col + 2];
        o.w = aw * invS + b2[col + 3];
        *(float4*)&out[dst * 64 + col] = o;
    }
}

// ---------------- launch: fork-join overlap of CSR build with GEMM1 ----------------
extern "C" void kernel_launch(void* const* d_in, const int* in_sizes, int n_in,
                              void* d_out, int out_size) {
    const float* x   = (const float*)d_in[0];
    const int*   ei  = (const int*)d_in[1];
    const float* W1  = (const float*)d_in[2];
    const float* as1 = (const float*)d_in[3];
    const float* ad1 = (const float*)d_in[4];
    const float* b1  = (const float*)d_in[5];
    const float* W2  = (const float*)d_in[6];
    const float* as2 = (const float*)d_in[7];
    const float* ad2 = (const float*)d_in[8];
    const float* b2  = (const float*)d_in[9];
    float* out = (float*)d_out;
    int E = in_sizes[1] / 2;
    int n4t = (E >> 2) + 1;  // int4 threads + 1 tail thread

    // One-time host-side resources (no device memory allocated).
    static cudaStream_t s_csr = nullptr;
    static cudaEvent_t  ev_fork = nullptr, ev_join = nullptr;
    static void* p_deg = nullptr;
    static void* p_pub = nullptr;
    if (s_csr == nullptr) {
        cudaStreamCreateWithFlags(&s_csr, cudaStreamNonBlocking);
        cudaEventCreateWithFlags(&ev_fork, cudaEventDisableTiming);
        cudaEventCreateWithFlags(&ev_join, cudaEventDisableTiming);
        cudaGetSymbolAddress(&p_deg, g_deg);
        cudaGetSymbolAddress(&p_pub, g_pub);
    }

    cudaStream_t s0 = 0;  // capture-origin (default) stream

    // Fork: CSR build chain runs on s_csr, independent of gemm1att1.
    cudaEventRecord(ev_fork, s0);
    cudaStreamWaitEvent(s_csr, ev_fork, 0);
    cudaMemsetAsync(p_deg, 0, (N_NODES + 4) * sizeof(int), s_csr);
    cudaMemsetAsync(p_pub, 0, SCAN_B * sizeof(int), s_csr);
    k_hist<<<(n4t + 255) / 256, 256, 0, s_csr>>>(ei, E);
    k_scan_lb<<<SCAN_B, 1024, 0, s_csr>>>();
    k_scatter<<<(n4t + 255) / 256, 256, 0, s_csr>>>(ei, E);
    cudaEventRecord(ev_join, s_csr);

    // Main chain on s0 (overlaps with CSR build).
    k_gemm1att1<<<N_NODES / 32, 128, 0, s0>>>(x, W1, as1, ad1);

    // Join: agg1 needs both xl1 (s0) and CSR (s_csr).
    cudaStreamWaitEvent(s0, ev_join, 0);
    k_agg1<<<N_NODES / 8, 256, 0, s0>>>(b1);
    k_gemm2att2<<<N_NODES / 32, 64, 0, s0>>>(W2, as2, ad2);
    k_agg2<<<N_NODES / 8, 256, 0, s0>>>(b2, out);
}

// round 15
// speedup vs baseline: 1.1812x; 1.1205x over previous
#include <cuda_runtime.h>
#include <math.h>

#define N_NODES 100000
#define E_MAX   1600000
#define FULL    0xffffffffu
#define N4      (N_NODES / 4)        // 25000 int4 groups
#define SCAN_B  ((N4 + 1023) / 1024) // 25 scan blocks
#define PUB_FLAG (1 << 30)

// ---------------- scratch (static __device__ — no dynamic alloc) ----------------
__device__ int   g_deg[N_NODES + 4];
__device__ int   g_off[N_NODES + 4];
__device__ int   g_cur[N_NODES + 4];
__device__ int   g_csr[E_MAX];
__device__ int   g_pub[SCAN_B];      // decoupled-lookback publish slots (memset to 0)

__device__ float g_xl1[N_NODES * 128];  // x @ W1
__device__ float g_as1[N_NODES * 8];    // a_src layer1
__device__ float g_ad1[N_NODES * 8];    // a_dst layer1
__device__ float g_h  [N_NODES * 128];  // elu(gat1 out)
__device__ float g_xl2[N_NODES * 64];   // h @ W2
__device__ float g_as2[N_NODES];
__device__ float g_ad2[N_NODES];

__device__ __forceinline__ float lrelu(float x) { return x > 0.f ? x : 0.2f * x; }
__device__ __forceinline__ float elu_f(float x) { return x > 0.f ? x : expm1f(x); }

// packed f32x2 helpers (FFMA2 — PTX-only, doubles fp32 FMA throughput on sm_103a)
__device__ __forceinline__ unsigned long long pk2(float lo, float hi) {
    unsigned long long r;
    asm("mov.b64 %0, {%1, %2};" : "=l"(r) : "f"(lo), "f"(hi));
    return r;
}
__device__ __forceinline__ void upk2(unsigned long long v, float& lo, float& hi) {
    asm("mov.b64 {%0, %1}, %2;" : "=f"(lo), "=f"(hi) : "l"(v));
}
__device__ __forceinline__ unsigned long long fma2(unsigned long long a,
                                                   unsigned long long b,
                                                   unsigned long long c) {
    unsigned long long d;
    asm("fma.rn.f32x2 %0, %1, %2, %3;" : "=l"(d) : "l"(a), "l"(b), "l"(c));
    return d;
}

// ---------------- CSR build ----------------
__global__ void k_hist(const int* __restrict__ ei, int E) {
    int t = blockIdx.x * blockDim.x + threadIdx.x;
    int n4 = E >> 2;
    const int4* d4 = (const int4*)(ei + E);
    if (t < n4) {
        int4 v = d4[t];
        atomicAdd(&g_deg[v.x], 1);
        atomicAdd(&g_deg[v.y], 1);
        atomicAdd(&g_deg[v.z], 1);
        atomicAdd(&g_deg[v.w], 1);
    } else if (t == n4) {
        for (int e = n4 * 4; e < E; e++) atomicAdd(&g_deg[ei[E + e]], 1);
    }
}

// ---- single-kernel scan with decoupled lookback (25 co-resident blocks) ----
__global__ void __launch_bounds__(1024) k_scan_lb() {
    __shared__ int warp_sums[32];
    __shared__ int s_carry;
    int tid = threadIdx.x, lane = tid & 31, wid = tid >> 5;
    int b = blockIdx.x;
    int i = b * 1024 + tid;
    const int4* deg4 = (const int4*)g_deg;
    int4* off4 = (int4*)g_off;
    int4* cur4 = (int4*)g_cur;

    int4 v = (i < N4) ? deg4[i] : make_int4(0, 0, 0, 0);
    int tot = v.x + v.y + v.z + v.w;
    int xs = tot;
    #pragma unroll
    for (int o = 1; o < 32; o <<= 1) {
        int t = __shfl_up_sync(FULL, xs, o);
        if (lane >= o) xs += t;
    }
    if (lane == 31) warp_sums[wid] = xs;
    __syncthreads();
    if (wid == 0) {
        int ws = warp_sums[lane];
        #pragma unroll
        for (int o = 1; o < 32; o <<= 1) {
            int t = __shfl_up_sync(FULL, ws, o);
            if (lane >= o) ws += t;
        }
        warp_sums[lane] = ws;
    }
    __syncthreads();

    // publish this block's total, then lookback over predecessors (warp 0)
    if (tid == 0) atomicExch(&g_pub[b], warp_sums[31] + PUB_FLAG);
    if (wid == 0) {
        int sum = 0;
        if (lane < b) {
            int val;
            do { val = atomicAdd(&g_pub[lane], 0); } while (val < PUB_FLAG);
            sum = val - PUB_FLAG;
        }
        #pragma unroll
        for (int o = 16; o > 0; o >>= 1) sum += __shfl_xor_sync(FULL, sum, o);
        if (lane == 0) s_carry = sum;
    }
    __syncthreads();

    int carry = s_carry;
    int incl = xs + (wid > 0 ? warp_sums[wid - 1] : 0);
    int b0 = carry + incl - tot;
    if (i < N4) {
        int4 o;
        o.x = b0;
        o.y = b0 + v.x;
        o.z = o.y + v.y;
        o.w = o.z + v.z;
        off4[i] = o;
        cur4[i] = o;
    }
    if (b == SCAN_B - 1 && tid == 0) g_off[N_NODES] = carry + warp_sums[31];
}

__global__ void k_scatter(const int* __restrict__ ei, int E) {
    int t = blockIdx.x * blockDim.x + threadIdx.x;
    int n4 = E >> 2;
    const int4* s4 = (const int4*)ei;
    const int4* d4 = (const int4*)(ei + E);
    if (t < n4) {
        int4 s = s4[t];
        int4 d = d4[t];
        g_csr[atomicAdd(&g_cur[d.x], 1)] = s.x;
        g_csr[atomicAdd(&g_cur[d.y], 1)] = s.y;
        g_csr[atomicAdd(&g_cur[d.z], 1)] = s.z;
        g_csr[atomicAdd(&g_cur[d.w], 1)] = s.w;
    } else if (t == n4) {
        for (int e = n4 * 4; e < E; e++)
            g_csr[atomicAdd(&g_cur[ei[E + e]], 1)] = ei[e];
    }
}

// ---------------- GEMM1 + att1 fused (2D register tiling) ----------------
// 32 rows x 128 cols per block, 128 threads. Thread (tr,tc): rows tr*8..+7,
// cols tc*4..+3 (16 f32x2 accumulators). Per k: 2 broadcast LDS.128 (x) +
// 1 LDS.128 (W from staged sW tile) -> 6 l1tex wavefronts/warp/k vs 12 before.
__global__ void __launch_bounds__(128) k_gemm1att1(const float* __restrict__ x,
                                                   const float* __restrict__ W,
                                                   const float* __restrict__ asv,
                                                   const float* __restrict__ adv) {
    __shared__ __align__(16) float sxT[128][36];
    __shared__ __align__(16) float sW[32][128];
    int t = threadIdx.x;
    int row0 = blockIdx.x * 32;
    #pragma unroll 8
    for (int r = 0; r < 32; r++)
        sxT[t][r] = x[(row0 + r) * 128 + t];

    int tr = t >> 5, tc = t & 31;   // warp = fixed tr; lane = tc
    int c0 = tc << 2;               // this thread's 4 output cols
    int rbase = tr << 3;            // this thread's 8 rows (local)

    // acc[j*4+p] = col c0+j, row-pair (rbase+2p, rbase+2p+1)
    unsigned long long acc[16];
    #pragma unroll
    for (int i = 0; i < 16; i++) acc[i] = 0ull;

    for (int kt = 0; kt < 128; kt += 32) {
        __syncthreads();   // sxT writes done (1st iter) / sW reads done (later iters)
        #pragma unroll
        for (int i = 0; i < 8; i++) {
            int idx = i * 512 + t * 4;
            int wr = idx >> 7, wc = idx & 127;
            *(float4*)&sW[wr][wc] = *(const float4*)&W[(kt + wr) * 128 + wc];
        }
        __syncthreads();
        #pragma unroll
        for (int kk = 0; kk < 32; kk++) {
            const float4* xr = (const float4*)&sxT[kt + kk][rbase];
            float4 xa = xr[0], xb = xr[1];
            float4 wv = *(const float4*)&sW[kk][c0];
            unsigned long long x01 = pk2(xa.x, xa.y);
            unsigned long long x23 = pk2(xa.z, xa.w);
            unsigned long long x45 = pk2(xb.x, xb.y);
            unsigned long long x67 = pk2(xb.z, xb.w);
            unsigned long long w0 = pk2(wv.x, wv.x);
            unsigned long long w1 = pk2(wv.y, wv.y);
            unsigned long long w2 = pk2(wv.z, wv.z);
            unsigned long long w3 = pk2(wv.w, wv.w);
            acc[0]  = fma2(x01, w0, acc[0]);
            acc[1]  = fma2(x23, w0, acc[1]);
            acc[2]  = fma2(x45, w0, acc[2]);
            acc[3]  = fma2(x67, w0, acc[3]);
            acc[4]  = fma2(x01, w1, acc[4]);
            acc[5]  = fma2(x23, w1, acc[5]);
            acc[6]  = fma2(x45, w1, acc[6]);
            acc[7]  = fma2(x67, w1, acc[7]);
            acc[8]  = fma2(x01, w2, acc[8]);
            acc[9]  = fma2(x23, w2, acc[9]);
            acc[10] = fma2(x45, w2, acc[10]);
            acc[11] = fma2(x67, w2, acc[11]);
            acc[12] = fma2(x01, w3, acc[12]);
            acc[13] = fma2(x23, w3, acc[13]);
            acc[14] = fma2(x45, w3, acc[14]);
            acc[15] = fma2(x67, w3, acc[15]);
        }
    }

    // epilogue: write xl1 (coalesced float4) + att1 logits per (row, head)
    float va0 = asv[c0], va1 = asv[c0 + 1], va2 = asv[c0 + 2], va3 = asv[c0 + 3];
    float vd0 = adv[c0], vd1 = adv[c0 + 1], vd2 = adv[c0 + 2], vd3 = adv[c0 + 3];
    int h = tc >> 2;   // head owned by this thread's 4 cols
    #pragma unroll
    for (int p = 0; p < 4; p++) {
        float o0l, o0h, o1l, o1h, o2l, o2h, o3l, o3h;
        upk2(acc[0 * 4 + p], o0l, o0h);
        upk2(acc[1 * 4 + p], o1l, o1h);
        upk2(acc[2 * 4 + p], o2l, o2h);
        upk2(acc[3 * 4 + p], o3l, o3h);
        int row_l = row0 + rbase + 2 * p;
        int row_h = row_l + 1;
        *(float4*)&g_xl1[row_l * 128 + c0] = make_float4(o0l, o1l, o2l, o3l);
        *(float4*)&g_xl1[row_h * 128 + c0] = make_float4(o0h, o1h, o2h, o3h);
        float sl = o0l * va0 + o1l * va1 + o2l * va2 + o3l * va3;
        float dl = o0l * vd0 + o1l * vd1 + o2l * vd2 + o3l * vd3;
        float sh = o0h * va0 + o1h * va1 + o2h * va2 + o3h * va3;
        float dh = o0h * vd0 + o1h * vd1 + o2h * vd2 + o3h * vd3;
        #pragma unroll
        for (int ofs = 1; ofs < 4; ofs <<= 1) {
            sl += __shfl_xor_sync(FULL, sl, ofs);
            dl += __shfl_xor_sync(FULL, dl, ofs);
            sh += __shfl_xor_sync(FULL, sh, ofs);
            dh += __shfl_xor_sync(FULL, dh, ofs);
        }
        if ((tc & 3) == 0) {
            g_as1[row_l * 8 + h] = sl;
            g_ad1[row_l * 8 + h] = dl;
            g_as1[row_h * 8 + h] = sh;
            g_ad1[row_h * 8 + h] = dh;
        }
    }
}

// ---------------- GEMM2 + att2 fused ----------------
__global__ void __launch_bounds__(64) k_gemm2att2(const float* __restrict__ W,
                                                  const float* __restrict__ asv,
                                                  const float* __restrict__ adv) {
    __shared__ __align__(16) float shT[128][36];
    __shared__ float red[2][32][2];
    int c = threadIdx.x;  // 0..63
    int row0 = blockIdx.x * 32;
    int k0 = c, k1 = c + 64;
    #pragma unroll 4
    for (int r = 0; r < 32; r++) {
        shT[k0][r] = g_h[(row0 + r) * 128 + k0];
        shT[k1][r] = g_h[(row0 + r) * 128 + k1];
    }
    __syncthreads();

    unsigned long long acc[16];
    #pragma unroll
    for (int i = 0; i < 16; i++) acc[i] = 0ull;

    #pragma unroll 4
    for (int k = 0; k < 128; k++) {
        float w = W[k * 64 + c];
        unsigned long long w2 = pk2(w, w);
        const float4* col4 = (const float4*)&shT[k][0];
        #pragma unroll
        for (int i = 0; i < 8; i++) {
            float4 a = col4[i];
            acc[2 * i]     = fma2(pk2(a.x, a.y), w2, acc[2 * i]);
            acc[2 * i + 1] = fma2(pk2(a.z, a.w), w2, acc[2 * i + 1]);
        }
    }

    float as_c = asv[c], ad_c = adv[c];
    int lane = c & 31, wrp = c >> 5;
    #pragma unroll
    for (int i = 0; i < 16; i++) {
        float o0, o1;
        upk2(acc[i], o0, o1);
        g_xl2[(row0 + 2 * i) * 64 + c] = o0;
        g_xl2[(row0 + 2 * i + 1) * 64 + c] = o1;
        float s0 = o0 * as_c, d0 = o0 * ad_c;
        float s1 = o1 * as_c, d1 = o1 * ad_c;
        #pragma unroll
        for (int ofs = 1; ofs < 32; ofs <<= 1) {
            s0 += __shfl_xor_sync(FULL, s0, ofs);
            d0 += __shfl_xor_sync(FULL, d0, ofs);
            s1 += __shfl_xor_sync(FULL, s1, ofs);
            d1 += __shfl_xor_sync(FULL, d1, ofs);
        }
        if (lane == 0) {
            red[wrp][2 * i][0] = s0;
            red[wrp][2 * i][1] = d0;
            red[wrp][2 * i + 1][0] = s1;
            red[wrp][2 * i + 1][1] = d1;
        }
    }
    __syncthreads();
    if (c < 32) {
        g_as2[row0 + c] = red[0][c][0] + red[1][c][0];
        g_ad2[row0 + c] = red[0][c][1] + red[1][c][1];
    }
}

// ---------------- layer-1 aggregation: one warp per node, SINGLE PASS ----------------
__global__ void __launch_bounds__(256) k_agg1(const float* __restrict__ b1) {
    int gw = (blockIdx.x * blockDim.x + threadIdx.x) >> 5;
    if (gw >= N_NODES) return;
    int lane = threadIdx.x & 31;
    int dst = gw;
    int beg = g_off[dst], end = g_off[dst + 1];
    int h = lane & 7, g = lane >> 3;
    int col = lane << 2, hs = lane >> 2;

    float adst = g_ad1[dst * 8 + h];
    float wself = __expf(lrelu(g_as1[dst * 8 + h] + adst));
    float denom = (g == 0) ? wself : 0.f;   // once per 8-lane residue class
    float wself_sel = __shfl_sync(FULL, wself, hs);
    float4 xv = *(const float4*)&g_xl1[dst * 128 + col];
    unsigned long long ws2 = pk2(wself_sel, wself_sel);
    unsigned long long a01 = fma2(pk2(xv.x, xv.y), ws2, 0ull);
    unsigned long long a23 = fma2(pk2(xv.z, xv.w), ws2, 0ull);

    for (int base = beg; base < end; base += 32) {
        int mycsr = (base + lane < end) ? g_csr[base + lane] : 0;
        int n = min(32, end - base);
        for (int sub = 0; sub < n; sub += 4) {
            int src_g = __shfl_sync(FULL, mycsr, sub + g);
            float e = lrelu(__ldg(&g_as1[src_g * 8 + h]) + adst);
            float w = ((sub + g) < n) ? __expf(e) : 0.f;
            denom += w;   // identical within 8-lane group; xor-8/16 tree counts once
            #pragma unroll
            for (int j = 0; j < 4; j++) {
                if (sub + j < n) {   // warp-uniform condition
                    int srcj = __shfl_sync(FULL, mycsr, sub + j);
                    float wsel = __shfl_sync(FULL, w, (j << 3) + hs);
                    float4 v = *(const float4*)&g_xl1[srcj * 128 + col];
                    unsigned long long w2 = pk2(wsel, wsel);
                    a01 = fma2(pk2(v.x, v.y), w2, a01);
                    a23 = fma2(pk2(v.z, v.w), w2, a23);
                }
            }
        }
    }
    denom += __shfl_xor_sync(FULL, denom, 8);
    denom += __shfl_xor_sync(FULL, denom, 16);
    float invS = 1.f / (denom + 1e-16f);
    float invS_sel = __shfl_sync(FULL, invS, hs);

    float ax, ay, az, aw;
    upk2(a01, ax, ay);
    upk2(a23, az, aw);
    float4 o;
    o.x = elu_f(ax * invS_sel + b1[col + 0]);
    o.y = elu_f(ay * invS_sel + b1[col + 1]);
    o.z = elu_f(az * invS_sel + b1[col + 2]);
    o.w = elu_f(aw * invS_sel + b1[col + 3]);
    *(float4*)&g_h[dst * 128 + col] = o;
}

// ---------------- layer-2 aggregation (H=1, C=64): split halves, SINGLE PASS ----------
__global__ void __launch_bounds__(256) k_agg2(const float* __restrict__ b2,
                                              float* __restrict__ out) {
    int gw = (blockIdx.x * blockDim.x + threadIdx.x) >> 5;
    if (gw >= N_NODES) return;
    int lane = threadIdx.x & 31;
    int q4 = lane >> 2;            // quad-group 0..7: weight for edge sub+q4
    int half = lane >> 4;          // 0/1: which 4-edge subgroup to accumulate
    int col = (lane & 15) << 2;    // feature cols
    int dst = gw;
    int beg = g_off[dst], end = g_off[dst + 1];

    float adst = g_ad2[dst];
    float wself = __expf(lrelu(g_as2[dst] + adst));
    float denom = (lane < 4) ? wself : 0.f;   // once per bits-0..1 residue class
    unsigned long long a01 = 0ull, a23 = 0ull;
    if (half == 0) {
        float4 xv = *(const float4*)&g_xl2[dst * 64 + col];
        unsigned long long ws2 = pk2(wself, wself);
        a01 = fma2(pk2(xv.x, xv.y), ws2, 0ull);
        a23 = fma2(pk2(xv.z, xv.w), ws2, 0ull);
    }

    for (int base = beg; base < end; base += 32) {
        int mycsr = (base + lane < end) ? g_csr[base + lane] : 0;
        int n = min(32, end - base);
        for (int sub = 0; sub < n; sub += 8) {
            int eidx = sub + q4;
            int src_q = __shfl_sync(FULL, mycsr, eidx & 31);
            float e = lrelu(__ldg(&g_as2[src_q]) + adst);
            float w = (eidx < n) ? __expf(e) : 0.f;
            denom += w;   // identical within quad; xor-4/8/16 counts once
            int jbase = sub + (half << 2);
            #pragma unroll
            for (int jj = 0; jj < 4; jj++) {
                int j = jbase + jj;
                // unconditional shfls — all 32 lanes participate
                int srcj = __shfl_sync(FULL, mycsr, j & 31);
                float wj = __shfl_sync(FULL, w, ((j - sub) & 7) << 2);
                if (j < n) {
                    float4 v = *(const float4*)&g_xl2[srcj * 64 + col];
                    unsigned long long w2 = pk2(wj, wj);
                    a01 = fma2(pk2(v.x, v.y), w2, a01);
                    a23 = fma2(pk2(v.z, v.w), w2, a23);
                }
            }
        }
    }
    denom += __shfl_xor_sync(FULL, denom, 4);
    denom += __shfl_xor_sync(FULL, denom, 8);
    denom += __shfl_xor_sync(FULL, denom, 16);
    float invS = 1.f / (denom + 1e-16f);
    float ax, ay, az, aw;
    upk2(a01, ax, ay);
    upk2(a23, az, aw);
    ax += __shfl_xor_sync(FULL, ax, 16);
    ay += __shfl_xor_sync(FULL, ay, 16);
    az += __shfl_xor_sync(FULL, az, 16);
    aw += __shfl_xor_sync(FULL, aw, 16);

    if (lane < 16) {
        float4 o;
        o.x = ax * invS + b2[col + 0];
        o.y = ay * invS + b2[col + 1];
        o.z = az * invS + b2[col + 2];
        o.w = aw * invS + b2[col + 3];
        *(float4*)&out[dst * 64 + col] = o;
    }
}

// ---------------- launch: fork-join overlap of CSR build with GEMM1 ----------------
extern "C" void kernel_launch(void* const* d_in, const int* in_sizes, int n_in,
                              void* d_out, int out_size) {
    const float* x   = (const float*)d_in[0];
    const int*   ei  = (const int*)d_in[1];
    const float* W1  = (const float*)d_in[2];
    const float* as1 = (const float*)d_in[3];
    const float* ad1 = (const float*)d_in[4];
    const float* b1  = (const float*)d_in[5];
    const float* W2  = (const float*)d_in[6];
    const float* as2 = (const float*)d_in[7];
    const float* ad2 = (const float*)d_in[8];
    const float* b2  = (const float*)d_in[9];
    float* out = (float*)d_out;
    int E = in_sizes[1] / 2;
    int n4t = (E >> 2) + 1;  // int4 threads + 1 tail thread

    // One-time host-side resources (no device memory allocated).
    static cudaStream_t s_csr = nullptr;
    static cudaEvent_t  ev_fork = nullptr, ev_join = nullptr;
    static void* p_deg = nullptr;
    static void* p_pub = nullptr;
    if (s_csr == nullptr) {
        cudaStreamCreateWithFlags(&s_csr, cudaStreamNonBlocking);
        cudaEventCreateWithFlags(&ev_fork, cudaEventDisableTiming);
        cudaEventCreateWithFlags(&ev_join, cudaEventDisableTiming);
        cudaGetSymbolAddress(&p_deg, g_deg);
        cudaGetSymbolAddress(&p_pub, g_pub);
    }

    cudaStream_t s0 = 0;  // capture-origin (default) stream

    // Fork: CSR build chain runs on s_csr, independent of gemm1att1.
    cudaEventRecord(ev_fork, s0);
    cudaStreamWaitEvent(s_csr, ev_fork, 0);
    cudaMemsetAsync(p_deg, 0, (N_NODES + 4) * sizeof(int), s_csr);
    cudaMemsetAsync(p_pub, 0, SCAN_B * sizeof(int), s_csr);
    k_hist<<<(n4t + 255) / 256, 256, 0, s_csr>>>(ei, E);
    k_scan_lb<<<SCAN_B, 1024, 0, s_csr>>>();
    k_scatter<<<(n4t + 255) / 256, 256, 0, s_csr>>>(ei, E);
    cudaEventRecord(ev_join, s_csr);

    // Main chain on s0 (overlaps with CSR build).
    k_gemm1att1<<<N_NODES / 32, 128, 0, s0>>>(x, W1, as1, ad1);

    // Join: agg1 needs both xl1 (s0) and CSR (s_csr).
    cudaStreamWaitEvent(s0, ev_join, 0);
    k_agg1<<<N_NODES / 8, 256, 0, s0>>>(b1);
    k_gemm2att2<<<N_NODES / 32, 64, 0, s0>>>(W2, as2, ad2);
    k_agg2<<<N_NODES / 8, 256, 0, s0>>>(b2, out);
}

// round 16
// speedup vs baseline: 1.2045x; 1.0197x over previous
#include <cuda_runtime.h>
#include <cuda_fp16.h>
#include <math.h>

#define N_NODES 100000
#define E_MAX   1600000
#define FULL    0xffffffffu
#define N4      (N_NODES / 4)        // 25000 int4 groups
#define SCAN_B  ((N4 + 1023) / 1024) // 25 scan blocks
#define PUB_FLAG (1 << 30)

// ---------------- scratch (static __device__ — no dynamic alloc) ----------------
__device__ int   g_deg[N_NODES + 4];
__device__ int   g_off[N_NODES + 4];
__device__ int   g_cur[N_NODES + 4];
__device__ int   g_csr[E_MAX];
__device__ int   g_pub[SCAN_B];      // decoupled-lookback publish slots (memset to 0)

__device__ __half2 g_xl1h[N_NODES * 64];  // x @ W1, fp16 (message values only)
__device__ float g_as1[N_NODES * 8];    // a_src layer1 (fp32)
__device__ float g_ad1[N_NODES * 8];    // a_dst layer1 (fp32)
__device__ float g_h  [N_NODES * 128];  // elu(gat1 out), fp32
__device__ float g_xl2[N_NODES * 64];   // h @ W2, fp32
__device__ float g_as2[N_NODES];
__device__ float g_ad2[N_NODES];

__device__ __forceinline__ float lrelu(float x) { return x > 0.f ? x : 0.2f * x; }
__device__ __forceinline__ float elu_f(float x) { return x > 0.f ? x : expm1f(x); }

// packed f32x2 helpers (FFMA2 — PTX-only, doubles fp32 FMA throughput on sm_103a)
__device__ __forceinline__ unsigned long long pk2(float lo, float hi) {
    unsigned long long r;
    asm("mov.b64 %0, {%1, %2};" : "=l"(r) : "f"(lo), "f"(hi));
    return r;
}
__device__ __forceinline__ void upk2(unsigned long long v, float& lo, float& hi) {
    asm("mov.b64 {%0, %1}, %2;" : "=f"(lo), "=f"(hi) : "l"(v));
}
__device__ __forceinline__ unsigned long long fma2(unsigned long long a,
                                                   unsigned long long b,
                                                   unsigned long long c) {
    unsigned long long d;
    asm("fma.rn.f32x2 %0, %1, %2, %3;" : "=l"(d) : "l"(a), "l"(b), "l"(c));
    return d;
}

// ---------------- CSR build ----------------
__global__ void k_hist(const int* __restrict__ ei, int E) {
    int t = blockIdx.x * blockDim.x + threadIdx.x;
    int n4 = E >> 2;
    const int4* d4 = (const int4*)(ei + E);
    if (t < n4) {
        int4 v = d4[t];
        atomicAdd(&g_deg[v.x], 1);
        atomicAdd(&g_deg[v.y], 1);
        atomicAdd(&g_deg[v.z], 1);
        atomicAdd(&g_deg[v.w], 1);
    } else if (t == n4) {
        for (int e = n4 * 4; e < E; e++) atomicAdd(&g_deg[ei[E + e]], 1);
    }
}

// ---- single-kernel scan with decoupled lookback (25 co-resident blocks) ----
__global__ void __launch_bounds__(1024) k_scan_lb() {
    __shared__ int warp_sums[32];
    __shared__ int s_carry;
    int tid = threadIdx.x, lane = tid & 31, wid = tid >> 5;
    int b = blockIdx.x;
    int i = b * 1024 + tid;
    const int4* deg4 = (const int4*)g_deg;
    int4* off4 = (int4*)g_off;
    int4* cur4 = (int4*)g_cur;

    int4 v = (i < N4) ? deg4[i] : make_int4(0, 0, 0, 0);
    int tot = v.x + v.y + v.z + v.w;
    int xs = tot;
    #pragma unroll
    for (int o = 1; o < 32; o <<= 1) {
        int t = __shfl_up_sync(FULL, xs, o);
        if (lane >= o) xs += t;
    }
    if (lane == 31) warp_sums[wid] = xs;
    __syncthreads();
    if (wid == 0) {
        int ws = warp_sums[lane];
        #pragma unroll
        for (int o = 1; o < 32; o <<= 1) {
            int t = __shfl_up_sync(FULL, ws, o);
            if (lane >= o) ws += t;
        }
        warp_sums[lane] = ws;
    }
    __syncthreads();

    if (tid == 0) atomicExch(&g_pub[b], warp_sums[31] + PUB_FLAG);
    if (wid == 0) {
        int sum = 0;
        if (lane < b) {
            int val;
            do { val = atomicAdd(&g_pub[lane], 0); } while (val < PUB_FLAG);
            sum = val - PUB_FLAG;
        }
        #pragma unroll
        for (int o = 16; o > 0; o >>= 1) sum += __shfl_xor_sync(FULL, sum, o);
        if (lane == 0) s_carry = sum;
    }
    __syncthreads();

    int carry = s_carry;
    int incl = xs + (wid > 0 ? warp_sums[wid - 1] : 0);
    int b0 = carry + incl - tot;
    if (i < N4) {
        int4 o;
        o.x = b0;
        o.y = b0 + v.x;
        o.z = o.y + v.y;
        o.w = o.z + v.z;
        off4[i] = o;
        cur4[i] = o;
    }
    if (b == SCAN_B - 1 && tid == 0) g_off[N_NODES] = carry + warp_sums[31];
}

__global__ void k_scatter(const int* __restrict__ ei, int E) {
    int t = blockIdx.x * blockDim.x + threadIdx.x;
    int n4 = E >> 2;
    const int4* s4 = (const int4*)ei;
    const int4* d4 = (const int4*)(ei + E);
    if (t < n4) {
        int4 s = s4[t];
        int4 d = d4[t];
        g_csr[atomicAdd(&g_cur[d.x], 1)] = s.x;
        g_csr[atomicAdd(&g_cur[d.y], 1)] = s.y;
        g_csr[atomicAdd(&g_cur[d.z], 1)] = s.z;
        g_csr[atomicAdd(&g_cur[d.w], 1)] = s.w;
    } else if (t == n4) {
        for (int e = n4 * 4; e < E; e++)
            g_csr[atomicAdd(&g_cur[ei[E + e]], 1)] = ei[e];
    }
}

// ---------------- GEMM1 + att1 fused (2D register tiling, fp16 xl1 out) ----------------
__global__ void __launch_bounds__(128) k_gemm1att1(const float* __restrict__ x,
                                                   const float* __restrict__ W,
                                                   const float* __restrict__ asv,
                                                   const float* __restrict__ adv) {
    __shared__ __align__(16) float sxT[128][36];
    __shared__ __align__(16) float sW[32][128];
    int t = threadIdx.x;
    int row0 = blockIdx.x * 32;
    #pragma unroll 8
    for (int r = 0; r < 32; r++)
        sxT[t][r] = x[(row0 + r) * 128 + t];

    int tr = t >> 5, tc = t & 31;
    int c0 = tc << 2;
    int rbase = tr << 3;

    unsigned long long acc[16];
    #pragma unroll
    for (int i = 0; i < 16; i++) acc[i] = 0ull;

    for (int kt = 0; kt < 128; kt += 32) {
        __syncthreads();
        #pragma unroll
        for (int i = 0; i < 8; i++) {
            int idx = i * 512 + t * 4;
            int wr = idx >> 7, wc = idx & 127;
            *(float4*)&sW[wr][wc] = *(const float4*)&W[(kt + wr) * 128 + wc];
        }
        __syncthreads();
        #pragma unroll
        for (int kk = 0; kk < 32; kk++) {
            const float4* xr = (const float4*)&sxT[kt + kk][rbase];
            float4 xa = xr[0], xb = xr[1];
            float4 wv = *(const float4*)&sW[kk][c0];
            unsigned long long x01 = pk2(xa.x, xa.y);
            unsigned long long x23 = pk2(xa.z, xa.w);
            unsigned long long x45 = pk2(xb.x, xb.y);
            unsigned long long x67 = pk2(xb.z, xb.w);
            unsigned long long w0 = pk2(wv.x, wv.x);
            unsigned long long w1 = pk2(wv.y, wv.y);
            unsigned long long w2 = pk2(wv.z, wv.z);
            unsigned long long w3 = pk2(wv.w, wv.w);
            acc[0]  = fma2(x01, w0, acc[0]);
            acc[1]  = fma2(x23, w0, acc[1]);
            acc[2]  = fma2(x45, w0, acc[2]);
            acc[3]  = fma2(x67, w0, acc[3]);
            acc[4]  = fma2(x01, w1, acc[4]);
            acc[5]  = fma2(x23, w1, acc[5]);
            acc[6]  = fma2(x45, w1, acc[6]);
            acc[7]  = fma2(x67, w1, acc[7]);
            acc[8]  = fma2(x01, w2, acc[8]);
            acc[9]  = fma2(x23, w2, acc[9]);
            acc[10] = fma2(x45, w2, acc[10]);
            acc[11] = fma2(x67, w2, acc[11]);
            acc[12] = fma2(x01, w3, acc[12]);
            acc[13] = fma2(x23, w3, acc[13]);
            acc[14] = fma2(x45, w3, acc[14]);
            acc[15] = fma2(x67, w3, acc[15]);
        }
    }

    // epilogue: write xl1 as fp16 (coalesced uint2) + fp32 att1 logits
    float va0 = asv[c0], va1 = asv[c0 + 1], va2 = asv[c0 + 2], va3 = asv[c0 + 3];
    float vd0 = adv[c0], vd1 = adv[c0 + 1], vd2 = adv[c0 + 2], vd3 = adv[c0 + 3];
    int h = tc >> 2;
    #pragma unroll
    for (int p = 0; p < 4; p++) {
        float o0l, o0h, o1l, o1h, o2l, o2h, o3l, o3h;
        upk2(acc[0 * 4 + p], o0l, o0h);
        upk2(acc[1 * 4 + p], o1l, o1h);
        upk2(acc[2 * 4 + p], o2l, o2h);
        upk2(acc[3 * 4 + p], o3l, o3h);
        int row_l = row0 + rbase + 2 * p;
        int row_h = row_l + 1;
        union { uint2 u; __half2 q[2]; } PL, PH;
        PL.q[0] = __floats2half2_rn(o0l, o1l);
        PL.q[1] = __floats2half2_rn(o2l, o3l);
        PH.q[0] = __floats2half2_rn(o0h, o1h);
        PH.q[1] = __floats2half2_rn(o2h, o3h);
        *(uint2*)&g_xl1h[row_l * 64 + (tc << 1)] = PL.u;
        *(uint2*)&g_xl1h[row_h * 64 + (tc << 1)] = PH.u;
        float sl = o0l * va0 + o1l * va1 + o2l * va2 + o3l * va3;
        float dl = o0l * vd0 + o1l * vd1 + o2l * vd2 + o3l * vd3;
        float sh = o0h * va0 + o1h * va1 + o2h * va2 + o3h * va3;
        float dh = o0h * vd0 + o1h * vd1 + o2h * vd2 + o3h * vd3;
        #pragma unroll
        for (int ofs = 1; ofs < 4; ofs <<= 1) {
            sl += __shfl_xor_sync(FULL, sl, ofs);
            dl += __shfl_xor_sync(FULL, dl, ofs);
            sh += __shfl_xor_sync(FULL, sh, ofs);
            dh += __shfl_xor_sync(FULL, dh, ofs);
        }
        if ((tc & 3) == 0) {
            g_as1[row_l * 8 + h] = sl;
            g_ad1[row_l * 8 + h] = dl;
            g_as1[row_h * 8 + h] = sh;
            g_ad1[row_h * 8 + h] = dh;
        }
    }
}

// ---------------- GEMM2 + att2 fused ----------------
__global__ void __launch_bounds__(64) k_gemm2att2(const float* __restrict__ W,
                                                  const float* __restrict__ asv,
                                                  const float* __restrict__ adv) {
    __shared__ __align__(16) float shT[128][36];
    __shared__ float red[2][32][2];
    int c = threadIdx.x;  // 0..63
    int row0 = blockIdx.x * 32;
    int k0 = c, k1 = c + 64;
    #pragma unroll 4
    for (int r = 0; r < 32; r++) {
        shT[k0][r] = g_h[(row0 + r) * 128 + k0];
        shT[k1][r] = g_h[(row0 + r) * 128 + k1];
    }
    __syncthreads();

    unsigned long long acc[16];
    #pragma unroll
    for (int i = 0; i < 16; i++) acc[i] = 0ull;

    #pragma unroll 4
    for (int k = 0; k < 128; k++) {
        float w = W[k * 64 + c];
        unsigned long long w2 = pk2(w, w);
        const float4* col4 = (const float4*)&shT[k][0];
        #pragma unroll
        for (int i = 0; i < 8; i++) {
            float4 a = col4[i];
            acc[2 * i]     = fma2(pk2(a.x, a.y), w2, acc[2 * i]);
            acc[2 * i + 1] = fma2(pk2(a.z, a.w), w2, acc[2 * i + 1]);
        }
    }

    float as_c = asv[c], ad_c = adv[c];
    int lane = c & 31, wrp = c >> 5;
    #pragma unroll
    for (int i = 0; i < 16; i++) {
        float o0, o1;
        upk2(acc[i], o0, o1);
        g_xl2[(row0 + 2 * i) * 64 + c] = o0;
        g_xl2[(row0 + 2 * i + 1) * 64 + c] = o1;
        float s0 = o0 * as_c, d0 = o0 * ad_c;
        float s1 = o1 * as_c, d1 = o1 * ad_c;
        #pragma unroll
        for (int ofs = 1; ofs < 32; ofs <<= 1) {
            s0 += __shfl_xor_sync(FULL, s0, ofs);
            d0 += __shfl_xor_sync(FULL, d0, ofs);
            s1 += __shfl_xor_sync(FULL, s1, ofs);
            d1 += __shfl_xor_sync(FULL, d1, ofs);
        }
        if (lane == 0) {
            red[wrp][2 * i][0] = s0;
            red[wrp][2 * i][1] = d0;
            red[wrp][2 * i + 1][0] = s1;
            red[wrp][2 * i + 1][1] = d1;
        }
    }
    __syncthreads();
    if (c < 32) {
        g_as2[row0 + c] = red[0][c][0] + red[1][c][0];
        g_ad2[row0 + c] = red[0][c][1] + red[1][c][1];
    }
}

// ---------------- layer-1 aggregation: one warp per node, SINGLE PASS, fp16 gathers ----
__global__ void __launch_bounds__(256) k_agg1(const float* __restrict__ b1) {
    int gw = (blockIdx.x * blockDim.x + threadIdx.x) >> 5;
    if (gw >= N_NODES) return;
    int lane = threadIdx.x & 31;
    int dst = gw;
    int beg = g_off[dst], end = g_off[dst + 1];
    int h = lane & 7, g = lane >> 3;
    int col = lane << 2, hs = lane >> 2;

    float adst = g_ad1[dst * 8 + h];
    float wself = __expf(lrelu(g_as1[dst * 8 + h] + adst));
    float denom = (g == 0) ? wself : 0.f;   // once per 8-lane residue class
    float wself_sel = __shfl_sync(FULL, wself, hs);
    union { uint2 u; __half2 q[2]; } SV;
    SV.u = *(const uint2*)&g_xl1h[dst * 64 + (lane << 1)];
    float2 sf0 = __half22float2(SV.q[0]);
    float2 sf1 = __half22float2(SV.q[1]);
    unsigned long long ws2 = pk2(wself_sel, wself_sel);
    unsigned long long a01 = fma2(pk2(sf0.x, sf0.y), ws2, 0ull);
    unsigned long long a23 = fma2(pk2(sf1.x, sf1.y), ws2, 0ull);

    for (int base = beg; base < end; base += 32) {
        int mycsr = (base + lane < end) ? g_csr[base + lane] : 0;
        int n = min(32, end - base);
        for (int sub = 0; sub < n; sub += 4) {
            int src_g = __shfl_sync(FULL, mycsr, sub + g);
            float e = lrelu(__ldg(&g_as1[src_g * 8 + h]) + adst);
            float w = ((sub + g) < n) ? __expf(e) : 0.f;
            denom += w;   // identical within 8-lane group; xor-8/16 tree counts once
            #pragma unroll
            for (int j = 0; j < 4; j++) {
                if (sub + j < n) {   // warp-uniform condition
                    int srcj = __shfl_sync(FULL, mycsr, sub + j);
                    float wsel = __shfl_sync(FULL, w, (j << 3) + hs);
                    union { uint2 u; __half2 q[2]; } V;
                    V.u = *(const uint2*)&g_xl1h[srcj * 64 + (lane << 1)];
                    float2 f0 = __half22float2(V.q[0]);
                    float2 f1 = __half22float2(V.q[1]);
                    unsigned long long w2 = pk2(wsel, wsel);
                    a01 = fma2(pk2(f0.x, f0.y), w2, a01);
                    a23 = fma2(pk2(f1.x, f1.y), w2, a23);
                }
            }
        }
    }
    denom += __shfl_xor_sync(FULL, denom, 8);
    denom += __shfl_xor_sync(FULL, denom, 16);
    float invS = 1.f / (denom + 1e-16f);
    float invS_sel = __shfl_sync(FULL, invS, hs);

    float ax, ay, az, aw;
    upk2(a01, ax, ay);
    upk2(a23, az, aw);
    float4 o;
    o.x = elu_f(ax * invS_sel + b1[col + 0]);
    o.y = elu_f(ay * invS_sel + b1[col + 1]);
    o.z = elu_f(az * invS_sel + b1[col + 2]);
    o.w = elu_f(aw * invS_sel + b1[col + 3]);
    *(float4*)&g_h[dst * 128 + col] = o;
}

// ---------------- layer-2 aggregation (H=1, C=64): split halves, SINGLE PASS ----------
__global__ void __launch_bounds__(256) k_agg2(const float* __restrict__ b2,
                                              float* __restrict__ out) {
    int gw = (blockIdx.x * blockDim.x + threadIdx.x) >> 5;
    if (gw >= N_NODES) return;
    int lane = threadIdx.x & 31;
    int q4 = lane >> 2;
    int half = lane >> 4;
    int col = (lane & 15) << 2;
    int dst = gw;
    int beg = g_off[dst], end = g_off[dst + 1];

    float adst = g_ad2[dst];
    float wself = __expf(lrelu(g_as2[dst] + adst));
    float denom = (lane < 4) ? wself : 0.f;
    unsigned long long a01 = 0ull, a23 = 0ull;
    if (half == 0) {
        float4 xv = *(const float4*)&g_xl2[dst * 64 + col];
        unsigned long long ws2 = pk2(wself, wself);
        a01 = fma2(pk2(xv.x, xv.y), ws2, 0ull);
        a23 = fma2(pk2(xv.z, xv.w), ws2, 0ull);
    }

    for (int base = beg; base < end; base += 32) {
        int mycsr = (base + lane < end) ? g_csr[base + lane] : 0;
        int n = min(32, end - base);
        for (int sub = 0; sub < n; sub += 8) {
            int eidx = sub + q4;
            int src_q = __shfl_sync(FULL, mycsr, eidx & 31);
            float e = lrelu(__ldg(&g_as2[src_q]) + adst);
            float w = (eidx < n) ? __expf(e) : 0.f;
            denom += w;
            int jbase = sub + (half << 2);
            #pragma unroll
            for (int jj = 0; jj < 4; jj++) {
                int j = jbase + jj;
                int srcj = __shfl_sync(FULL, mycsr, j & 31);
                float wj = __shfl_sync(FULL, w, ((j - sub) & 7) << 2);
                if (j < n) {
                    float4 v = *(const float4*)&g_xl2[srcj * 64 + col];
                    unsigned long long w2 = pk2(wj, wj);
                    a01 = fma2(pk2(v.x, v.y), w2, a01);
                    a23 = fma2(pk2(v.z, v.w), w2, a23);
                }
            }
        }
    }
    denom += __shfl_xor_sync(FULL, denom, 4);
    denom += __shfl_xor_sync(FULL, denom, 8);
    denom += __shfl_xor_sync(FULL, denom, 16);
    float invS = 1.f / (denom + 1e-16f);
    float ax, ay, az, aw;
    upk2(a01, ax, ay);
    upk2(a23, az, aw);
    ax += __shfl_xor_sync(FULL, ax, 16);
    ay += __shfl_xor_sync(FULL, ay, 16);
    az += __shfl_xor_sync(FULL, az, 16);
    aw += __shfl_xor_sync(FULL, aw, 16);

    if (lane < 16) {
        float4 o;
        o.x = ax * invS + b2[col + 0];
        o.y = ay * invS + b2[col + 1];
        o.z = az * invS + b2[col + 2];
        o.w = aw * invS + b2[col + 3];
        *(float4*)&out[dst * 64 + col] = o;
    }
}

// ---------------- launch: fork-join overlap of CSR build with GEMM1 ----------------
extern "C" void kernel_launch(void* const* d_in, const int* in_sizes, int n_in,
                              void* d_out, int out_size) {
    const float* x   = (const float*)d_in[0];
    const int*   ei  = (const int*)d_in[1];
    const float* W1  = (const float*)d_in[2];
    const float* as1 = (const float*)d_in[3];
    const float* ad1 = (const float*)d_in[4];
    const float* b1  = (const float*)d_in[5];
    const float* W2  = (const float*)d_in[6];
    const float* as2 = (const float*)d_in[7];
    const float* ad2 = (const float*)d_in[8];
    const float* b2  = (const float*)d_in[9];
    float* out = (float*)d_out;
    int E = in_sizes[1] / 2;
    int n4t = (E >> 2) + 1;  // int4 threads + 1 tail thread

    // One-time host-side resources (no device memory allocated).
    static cudaStream_t s_csr = nullptr;
    static cudaEvent_t  ev_fork = nullptr, ev_join = nullptr;
    static void* p_deg = nullptr;
    static void* p_pub = nullptr;
    if (s_csr == nullptr) {
        cudaStreamCreateWithFlags(&s_csr, cudaStreamNonBlocking);
        cudaEventCreateWithFlags(&ev_fork, cudaEventDisableTiming);
        cudaEventCreateWithFlags(&ev_join, cudaEventDisableTiming);
        cudaGetSymbolAddress(&p_deg, g_deg);
        cudaGetSymbolAddress(&p_pub, g_pub);
    }

    cudaStream_t s0 = 0;  // capture-origin (default) stream

    // Fork: CSR build chain runs on s_csr, independent of gemm1att1.
    cudaEventRecord(ev_fork, s0);
    cudaStreamWaitEvent(s_csr, ev_fork, 0);
    cudaMemsetAsync(p_deg, 0, (N_NODES + 4) * sizeof(int), s_csr);
    cudaMemsetAsync(p_pub, 0, SCAN_B * sizeof(int), s_csr);
    k_hist<<<(n4t + 255) / 256, 256, 0, s_csr>>>(ei, E);
    k_scan_lb<<<SCAN_B, 1024, 0, s_csr>>>();
    k_scatter<<<(n4t + 255) / 256, 256, 0, s_csr>>>(ei, E);
    cudaEventRecord(ev_join, s_csr);

    // Main chain on s0 (overlaps with CSR build).
    k_gemm1att1<<<N_NODES / 32, 128, 0, s0>>>(x, W1, as1, ad1);

    // Join: agg1 needs both xl1 (s0) and CSR (s_csr).
    cudaStreamWaitEvent(s0, ev_join, 0);
    k_agg1<<<N_NODES / 8, 256, 0, s0>>>(b1);
    k_gemm2att2<<<N_NODES / 32, 64, 0, s0>>>(W2, as2, ad2);
    k_agg2<<<N_NODES / 8, 256, 0, s0>>>(b2, out);
}

// round 17
// speedup vs baseline: 1.2177x; 1.0109x over previous
#include <cuda_runtime.h>
#include <cuda_fp16.h>
#include <math.h>

#define N_NODES 100000
#define E_MAX   1600000
#define FULL    0xffffffffu
#define N4      (N_NODES / 4)        // 25000 int4 groups
#define SCAN_B  ((N4 + 1023) / 1024) // 25 scan blocks
#define PUB_FLAG (1 << 30)

// ---------------- scratch (static __device__ — no dynamic alloc) ----------------
__device__ int   g_deg[N_NODES + 4];
__device__ int   g_off[N_NODES + 4];
__device__ int   g_cur[N_NODES + 4];
__device__ int   g_csr[E_MAX];
__device__ int   g_pub[SCAN_B];      // decoupled-lookback publish slots (cleared in k_hist)

__device__ __half2 g_xl1h[N_NODES * 64];  // x @ W1, fp16 (message values only)
__device__ float g_as1[N_NODES * 8];    // a_src layer1 (fp32)
__device__ float g_ad1[N_NODES * 8];    // a_dst layer1 (fp32)
__device__ float g_h  [N_NODES * 128];  // elu(gat1 out), fp32
__device__ __half g_xl2h[N_NODES * 64]; // h @ W2, fp16 (message values only)
__device__ float g_as2[N_NODES];
__device__ float g_ad2[N_NODES];

__device__ __forceinline__ float lrelu(float x) { return x > 0.f ? x : 0.2f * x; }
__device__ __forceinline__ float elu_f(float x) { return x > 0.f ? x : expm1f(x); }

// packed f32x2 helpers (FFMA2 — PTX-only, doubles fp32 FMA throughput on sm_103a)
__device__ __forceinline__ unsigned long long pk2(float lo, float hi) {
    unsigned long long r;
    asm("mov.b64 %0, {%1, %2};" : "=l"(r) : "f"(lo), "f"(hi));
    return r;
}
__device__ __forceinline__ void upk2(unsigned long long v, float& lo, float& hi) {
    asm("mov.b64 {%0, %1}, %2;" : "=f"(lo), "=f"(hi) : "l"(v));
}
__device__ __forceinline__ unsigned long long fma2(unsigned long long a,
                                                   unsigned long long b,
                                                   unsigned long long c) {
    unsigned long long d;
    asm("fma.rn.f32x2 %0, %1, %2, %3;" : "=l"(d) : "l"(a), "l"(b), "l"(c));
    return d;
}

// ---------------- CSR build ----------------
__global__ void k_hist(const int* __restrict__ ei, int E) {
    int t = blockIdx.x * blockDim.x + threadIdx.x;
    if (t < SCAN_B) g_pub[t] = 0;   // clear lookback slots (scan_lb runs after us)
    int n4 = E >> 2;
    const int4* d4 = (const int4*)(ei + E);
    if (t < n4) {
        int4 v = d4[t];
        atomicAdd(&g_deg[v.x], 1);
        atomicAdd(&g_deg[v.y], 1);
        atomicAdd(&g_deg[v.z], 1);
        atomicAdd(&g_deg[v.w], 1);
    } else if (t == n4) {
        for (int e = n4 * 4; e < E; e++) atomicAdd(&g_deg[ei[E + e]], 1);
    }
}

// ---- single-kernel scan with decoupled lookback (25 co-resident blocks) ----
__global__ void __launch_bounds__(1024) k_scan_lb() {
    __shared__ int warp_sums[32];
    __shared__ int s_carry;
    int tid = threadIdx.x, lane = tid & 31, wid = tid >> 5;
    int b = blockIdx.x;
    int i = b * 1024 + tid;
    const int4* deg4 = (const int4*)g_deg;
    int4* off4 = (int4*)g_off;
    int4* cur4 = (int4*)g_cur;

    int4 v = (i < N4) ? deg4[i] : make_int4(0, 0, 0, 0);
    int tot = v.x + v.y + v.z + v.w;
    int xs = tot;
    #pragma unroll
    for (int o = 1; o < 32; o <<= 1) {
        int t = __shfl_up_sync(FULL, xs, o);
        if (lane >= o) xs += t;
    }
    if (lane == 31) warp_sums[wid] = xs;
    __syncthreads();
    if (wid == 0) {
        int ws = warp_sums[lane];
        #pragma unroll
        for (int o = 1; o < 32; o <<= 1) {
            int t = __shfl_up_sync(FULL, ws, o);
            if (lane >= o) ws += t;
        }
        warp_sums[lane] = ws;
    }
    __syncthreads();

    if (tid == 0) atomicExch(&g_pub[b], warp_sums[31] + PUB_FLAG);
    if (wid == 0) {
        int sum = 0;
        if (lane < b) {
            int val;
            do { val = atomicAdd(&g_pub[lane], 0); } while (val < PUB_FLAG);
            sum = val - PUB_FLAG;
        }
        #pragma unroll
        for (int o = 16; o > 0; o >>= 1) sum += __shfl_xor_sync(FULL, sum, o);
        if (lane == 0) s_carry = sum;
    }
    __syncthreads();

    int carry = s_carry;
    int incl = xs + (wid > 0 ? warp_sums[wid - 1] : 0);
    int b0 = carry + incl - tot;
    if (i < N4) {
        int4 o;
        o.x = b0;
        o.y = b0 + v.x;
        o.z = o.y + v.y;
        o.w = o.z + v.z;
        off4[i] = o;
        cur4[i] = o;
    }
    if (b == SCAN_B - 1 && tid == 0) g_off[N_NODES] = carry + warp_sums[31];
}

__global__ void k_scatter(const int* __restrict__ ei, int E) {
    int t = blockIdx.x * blockDim.x + threadIdx.x;
    int n4 = E >> 2;
    const int4* s4 = (const int4*)ei;
    const int4* d4 = (const int4*)(ei + E);
    if (t < n4) {
        int4 s = s4[t];
        int4 d = d4[t];
        g_csr[atomicAdd(&g_cur[d.x], 1)] = s.x;
        g_csr[atomicAdd(&g_cur[d.y], 1)] = s.y;
        g_csr[atomicAdd(&g_cur[d.z], 1)] = s.z;
        g_csr[atomicAdd(&g_cur[d.w], 1)] = s.w;
    } else if (t == n4) {
        for (int e = n4 * 4; e < E; e++)
            g_csr[atomicAdd(&g_cur[ei[E + e]], 1)] = ei[e];
    }
}

// ---------------- GEMM1 + att1 fused (2D register tiling, fp16 xl1 out) ----------------
__global__ void __launch_bounds__(128) k_gemm1att1(const float* __restrict__ x,
                                                   const float* __restrict__ W,
                                                   const float* __restrict__ asv,
                                                   const float* __restrict__ adv) {
    __shared__ __align__(16) float sxT[128][36];
    __shared__ __align__(16) float sW[32][128];
    int t = threadIdx.x;
    int row0 = blockIdx.x * 32;
    #pragma unroll 8
    for (int r = 0; r < 32; r++)
        sxT[t][r] = x[(row0 + r) * 128 + t];

    int tr = t >> 5, tc = t & 31;
    int c0 = tc << 2;
    int rbase = tr << 3;

    unsigned long long acc[16];
    #pragma unroll
    for (int i = 0; i < 16; i++) acc[i] = 0ull;

    for (int kt = 0; kt < 128; kt += 32) {
        __syncthreads();
        #pragma unroll
        for (int i = 0; i < 8; i++) {
            int idx = i * 512 + t * 4;
            int wr = idx >> 7, wc = idx & 127;
            *(float4*)&sW[wr][wc] = *(const float4*)&W[(kt + wr) * 128 + wc];
        }
        __syncthreads();
        #pragma unroll
        for (int kk = 0; kk < 32; kk++) {
            const float4* xr = (const float4*)&sxT[kt + kk][rbase];
            float4 xa = xr[0], xb = xr[1];
            float4 wv = *(const float4*)&sW[kk][c0];
            unsigned long long x01 = pk2(xa.x, xa.y);
            unsigned long long x23 = pk2(xa.z, xa.w);
            unsigned long long x45 = pk2(xb.x, xb.y);
            unsigned long long x67 = pk2(xb.z, xb.w);
            unsigned long long w0 = pk2(wv.x, wv.x);
            unsigned long long w1 = pk2(wv.y, wv.y);
            unsigned long long w2 = pk2(wv.z, wv.z);
            unsigned long long w3 = pk2(wv.w, wv.w);
            acc[0]  = fma2(x01, w0, acc[0]);
            acc[1]  = fma2(x23, w0, acc[1]);
            acc[2]  = fma2(x45, w0, acc[2]);
            acc[3]  = fma2(x67, w0, acc[3]);
            acc[4]  = fma2(x01, w1, acc[4]);
            acc[5]  = fma2(x23, w1, acc[5]);
            acc[6]  = fma2(x45, w1, acc[6]);
            acc[7]  = fma2(x67, w1, acc[7]);
            acc[8]  = fma2(x01, w2, acc[8]);
            acc[9]  = fma2(x23, w2, acc[9]);
            acc[10] = fma2(x45, w2, acc[10]);
            acc[11] = fma2(x67, w2, acc[11]);
            acc[12] = fma2(x01, w3, acc[12]);
            acc[13] = fma2(x23, w3, acc[13]);
            acc[14] = fma2(x45, w3, acc[14]);
            acc[15] = fma2(x67, w3, acc[15]);
        }
    }

    // epilogue: write xl1 as fp16 (coalesced uint2) + fp32 att1 logits
    float va0 = asv[c0], va1 = asv[c0 + 1], va2 = asv[c0 + 2], va3 = asv[c0 + 3];
    float vd0 = adv[c0], vd1 = adv[c0 + 1], vd2 = adv[c0 + 2], vd3 = adv[c0 + 3];
    int h = tc >> 2;
    #pragma unroll
    for (int p = 0; p < 4; p++) {
        float o0l, o0h, o1l, o1h, o2l, o2h, o3l, o3h;
        upk2(acc[0 * 4 + p], o0l, o0h);
        upk2(acc[1 * 4 + p], o1l, o1h);
        upk2(acc[2 * 4 + p], o2l, o2h);
        upk2(acc[3 * 4 + p], o3l, o3h);
        int row_l = row0 + rbase + 2 * p;
        int row_h = row_l + 1;
        union { uint2 u; __half2 q[2]; } PL, PH;
        PL.q[0] = __floats2half2_rn(o0l, o1l);
        PL.q[1] = __floats2half2_rn(o2l, o3l);
        PH.q[0] = __floats2half2_rn(o0h, o1h);
        PH.q[1] = __floats2half2_rn(o2h, o3h);
        *(uint2*)&g_xl1h[row_l * 64 + (tc << 1)] = PL.u;
        *(uint2*)&g_xl1h[row_h * 64 + (tc << 1)] = PH.u;
        float sl = o0l * va0 + o1l * va1 + o2l * va2 + o3l * va3;
        float dl = o0l * vd0 + o1l * vd1 + o2l * vd2 + o3l * vd3;
        float sh = o0h * va0 + o1h * va1 + o2h * va2 + o3h * va3;
        float dh = o0h * vd0 + o1h * vd1 + o2h * vd2 + o3h * vd3;
        #pragma unroll
        for (int ofs = 1; ofs < 4; ofs <<= 1) {
            sl += __shfl_xor_sync(FULL, sl, ofs);
            dl += __shfl_xor_sync(FULL, dl, ofs);
            sh += __shfl_xor_sync(FULL, sh, ofs);
            dh += __shfl_xor_sync(FULL, dh, ofs);
        }
        if ((tc & 3) == 0) {
            g_as1[row_l * 8 + h] = sl;
            g_ad1[row_l * 8 + h] = dl;
            g_as1[row_h * 8 + h] = sh;
            g_ad1[row_h * 8 + h] = dh;
        }
    }
}

// ---------------- GEMM2 + att2 fused (fp16 xl2 out) ----------------
__global__ void __launch_bounds__(64) k_gemm2att2(const float* __restrict__ W,
                                                  const float* __restrict__ asv,
                                                  const float* __restrict__ adv) {
    __shared__ __align__(16) float shT[128][36];
    __shared__ float red[2][32][2];
    int c = threadIdx.x;  // 0..63
    int row0 = blockIdx.x * 32;
    int k0 = c, k1 = c + 64;
    #pragma unroll 4
    for (int r = 0; r < 32; r++) {
        shT[k0][r] = g_h[(row0 + r) * 128 + k0];
        shT[k1][r] = g_h[(row0 + r) * 128 + k1];
    }
    __syncthreads();

    unsigned long long acc[16];
    #pragma unroll
    for (int i = 0; i < 16; i++) acc[i] = 0ull;

    #pragma unroll 4
    for (int k = 0; k < 128; k++) {
        float w = W[k * 64 + c];
        unsigned long long w2 = pk2(w, w);
        const float4* col4 = (const float4*)&shT[k][0];
        #pragma unroll
        for (int i = 0; i < 8; i++) {
            float4 a = col4[i];
            acc[2 * i]     = fma2(pk2(a.x, a.y), w2, acc[2 * i]);
            acc[2 * i + 1] = fma2(pk2(a.z, a.w), w2, acc[2 * i + 1]);
        }
    }

    float as_c = asv[c], ad_c = adv[c];
    int lane = c & 31, wrp = c >> 5;
    #pragma unroll
    for (int i = 0; i < 16; i++) {
        float o0, o1;
        upk2(acc[i], o0, o1);
        g_xl2h[(row0 + 2 * i) * 64 + c] = __float2half_rn(o0);
        g_xl2h[(row0 + 2 * i + 1) * 64 + c] = __float2half_rn(o1);
        float s0 = o0 * as_c, d0 = o0 * ad_c;
        float s1 = o1 * as_c, d1 = o1 * ad_c;
        #pragma unroll
        for (int ofs = 1; ofs < 32; ofs <<= 1) {
            s0 += __shfl_xor_sync(FULL, s0, ofs);
            d0 += __shfl_xor_sync(FULL, d0, ofs);
            s1 += __shfl_xor_sync(FULL, s1, ofs);
            d1 += __shfl_xor_sync(FULL, d1, ofs);
        }
        if (lane == 0) {
            red[wrp][2 * i][0] = s0;
            red[wrp][2 * i][1] = d0;
            red[wrp][2 * i + 1][0] = s1;
            red[wrp][2 * i + 1][1] = d1;
        }
    }
    __syncthreads();
    if (c < 32) {
        g_as2[row0 + c] = red[0][c][0] + red[1][c][0];
        g_ad2[row0 + c] = red[0][c][1] + red[1][c][1];
    }
}

// ---------------- layer-1 aggregation: one warp per node, SINGLE PASS, fp16 gathers ----
__global__ void __launch_bounds__(256) k_agg1(const float* __restrict__ b1) {
    int gw = (blockIdx.x * blockDim.x + threadIdx.x) >> 5;
    if (gw >= N_NODES) return;
    int lane = threadIdx.x & 31;
    int dst = gw;
    int beg = g_off[dst], end = g_off[dst + 1];
    int h = lane & 7, g = lane >> 3;
    int col = lane << 2, hs = lane >> 2;

    float adst = g_ad1[dst * 8 + h];
    float wself = __expf(lrelu(g_as1[dst * 8 + h] + adst));
    float denom = (g == 0) ? wself : 0.f;   // once per 8-lane residue class
    float wself_sel = __shfl_sync(FULL, wself, hs);
    union { uint2 u; __half2 q[2]; } SV;
    SV.u = *(const uint2*)&g_xl1h[dst * 64 + (lane << 1)];
    float2 sf0 = __half22float2(SV.q[0]);
    float2 sf1 = __half22float2(SV.q[1]);
    unsigned long long ws2 = pk2(wself_sel, wself_sel);
    unsigned long long a01 = fma2(pk2(sf0.x, sf0.y), ws2, 0ull);
    unsigned long long a23 = fma2(pk2(sf1.x, sf1.y), ws2, 0ull);

    for (int base = beg; base < end; base += 32) {
        int mycsr = (base + lane < end) ? g_csr[base + lane] : 0;
        int n = min(32, end - base);
        for (int sub = 0; sub < n; sub += 4) {
            int src_g = __shfl_sync(FULL, mycsr, sub + g);
            float e = lrelu(__ldg(&g_as1[src_g * 8 + h]) + adst);
            float w = ((sub + g) < n) ? __expf(e) : 0.f;
            denom += w;   // identical within 8-lane group; xor-8/16 tree counts once
            #pragma unroll
            for (int j = 0; j < 4; j++) {
                if (sub + j < n) {   // warp-uniform condition
                    int srcj = __shfl_sync(FULL, mycsr, sub + j);
                    float wsel = __shfl_sync(FULL, w, (j << 3) + hs);
                    union { uint2 u; __half2 q[2]; } V;
                    V.u = *(const uint2*)&g_xl1h[srcj * 64 + (lane << 1)];
                    float2 f0 = __half22float2(V.q[0]);
                    float2 f1 = __half22float2(V.q[1]);
                    unsigned long long w2 = pk2(wsel, wsel);
                    a01 = fma2(pk2(f0.x, f0.y), w2, a01);
                    a23 = fma2(pk2(f1.x, f1.y), w2, a23);
                }
            }
        }
    }
    denom += __shfl_xor_sync(FULL, denom, 8);
    denom += __shfl_xor_sync(FULL, denom, 16);
    float invS = 1.f / (denom + 1e-16f);
    float invS_sel = __shfl_sync(FULL, invS, hs);

    float ax, ay, az, aw;
    upk2(a01, ax, ay);
    upk2(a23, az, aw);
    float4 o;
    o.x = elu_f(ax * invS_sel + b1[col + 0]);
    o.y = elu_f(ay * invS_sel + b1[col + 1]);
    o.z = elu_f(az * invS_sel + b1[col + 2]);
    o.w = elu_f(aw * invS_sel + b1[col + 3]);
    *(float4*)&g_h[dst * 128 + col] = o;
}

// ---------------- layer-2 aggregation: split halves, SINGLE PASS, fp16 gathers -------
__global__ void __launch_bounds__(256) k_agg2(const float* __restrict__ b2,
                                              float* __restrict__ out) {
    int gw = (blockIdx.x * blockDim.x + threadIdx.x) >> 5;
    if (gw >= N_NODES) return;
    int lane = threadIdx.x & 31;
    int q4 = lane >> 2;
    int half = lane >> 4;
    int col = (lane & 15) << 2;
    int dst = gw;
    int beg = g_off[dst], end = g_off[dst + 1];

    float adst = g_ad2[dst];
    float wself = __expf(lrelu(g_as2[dst] + adst));
    float denom = (lane < 4) ? wself : 0.f;
    unsigned long long a01 = 0ull, a23 = 0ull;
    if (half == 0) {
        union { uint2 u; __half2 q[2]; } SV;
        SV.u = *(const uint2*)&g_xl2h[dst * 64 + col];
        float2 sf0 = __half22float2(SV.q[0]);
        float2 sf1 = __half22float2(SV.q[1]);
        unsigned long long ws2 = pk2(wself, wself);
        a01 = fma2(pk2(sf0.x, sf0.y), ws2, 0ull);
        a23 = fma2(pk2(sf1.x, sf1.y), ws2, 0ull);
    }

    for (int base = beg; base < end; base += 32) {
        int mycsr = (base + lane < end) ? g_csr[base + lane] : 0;
        int n = min(32, end - base);
        for (int sub = 0; sub < n; sub += 8) {
            int eidx = sub + q4;
            int src_q = __shfl_sync(FULL, mycsr, eidx & 31);
            float e = lrelu(__ldg(&g_as2[src_q]) + adst);
            float w = (eidx < n) ? __expf(e) : 0.f;
            denom += w;
            int jbase = sub + (half << 2);
            #pragma unroll
            for (int jj = 0; jj < 4; jj++) {
                int j = jbase + jj;
                int srcj = __shfl_sync(FULL, mycsr, j & 31);
                float wj = __shfl_sync(FULL, w, ((j - sub) & 7) << 2);
                if (j < n) {
                    union { uint2 u; __half2 q[2]; } V;
                    V.u = *(const uint2*)&g_xl2h[srcj * 64 + col];
                    float2 f0 = __half22float2(V.q[0]);
                    float2 f1 = __half22float2(V.q[1]);
                    unsigned long long w2 = pk2(wj, wj);
                    a01 = fma2(pk2(f0.x, f0.y), w2, a01);
                    a23 = fma2(pk2(f1.x, f1.y), w2, a23);
                }
            }
        }
    }
    denom += __shfl_xor_sync(FULL, denom, 4);
    denom += __shfl_xor_sync(FULL, denom, 8);
    denom += __shfl_xor_sync(FULL, denom, 16);
    float invS = 1.f / (denom + 1e-16f);
    float ax, ay, az, aw;
    upk2(a01, ax, ay);
    upk2(a23, az, aw);
    ax += __shfl_xor_sync(FULL, ax, 16);
    ay += __shfl_xor_sync(FULL, ay, 16);
    az += __shfl_xor_sync(FULL, az, 16);
    aw += __shfl_xor_sync(FULL, aw, 16);

    if (lane < 16) {
        float4 o;
        o.x = ax * invS + b2[col + 0];
        o.y = ay * invS + b2[col + 1];
        o.z = az * invS + b2[col + 2];
        o.w = aw * invS + b2[col + 3];
        *(float4*)&out[dst * 64 + col] = o;
    }
}

// ---------------- launch: fork-join overlap of CSR build with GEMM1 ----------------
extern "C" void kernel_launch(void* const* d_in, const int* in_sizes, int n_in,
                              void* d_out, int out_size) {
    const float* x   = (const float*)d_in[0];
    const int*   ei  = (const int*)d_in[1];
    const float* W1  = (const float*)d_in[2];
    const float* as1 = (const float*)d_in[3];
    const float* ad1 = (const float*)d_in[4];
    const float* b1  = (const float*)d_in[5];
    const float* W2  = (const float*)d_in[6];
    const float* as2 = (const float*)d_in[7];
    const float* ad2 = (const float*)d_in[8];
    const float* b2  = (const float*)d_in[9];
    float* out = (float*)d_out;
    int E = in_sizes[1] / 2;
    int n4t = (E >> 2) + 1;  // int4 threads + 1 tail thread

    // One-time host-side resources (no device memory allocated).
    static cudaStream_t s_csr = nullptr;
    static cudaEvent_t  ev_fork = nullptr, ev_join = nullptr;
    static void* p_deg = nullptr;
    if (s_csr == nullptr) {
        cudaStreamCreateWithFlags(&s_csr, cudaStreamNonBlocking);
        cudaEventCreateWithFlags(&ev_fork, cudaEventDisableTiming);
        cudaEventCreateWithFlags(&ev_join, cudaEventDisableTiming);
        cudaGetSymbolAddress(&p_deg, g_deg);
    }

    cudaStream_t s0 = 0;  // capture-origin (default) stream

    // Fork point BEFORE gemm1 so the CSR chain overlaps it.
    cudaEventRecord(ev_fork, s0);

    // Main chain kernel first (launch index 0 → ncu -s 5 lands on agg1).
    k_gemm1att1<<<N_NODES / 32, 128, 0, s0>>>(x, W1, as1, ad1);

    // CSR build chain on s_csr (g_pub cleared inside k_hist).
    cudaStreamWaitEvent(s_csr, ev_fork, 0);
    cudaMemsetAsync(p_deg, 0, (N_NODES + 4) * sizeof(int), s_csr);
    k_hist<<<(n4t + 255) / 256, 256, 0, s_csr>>>(ei, E);
    k_scan_lb<<<SCAN_B, 1024, 0, s_csr>>>();
    k_scatter<<<(n4t + 255) / 256, 256, 0, s_csr>>>(ei, E);
    cudaEventRecord(ev_join, s_csr);

    // Join: agg1 needs both xl1 (s0) and CSR (s_csr).
    cudaStreamWaitEvent(s0, ev_join, 0);
    k_agg1<<<N_NODES / 8, 256, 0, s0>>>(b1);
    k_gemm2att2<<<N_NODES / 32, 64, 0, s0>>>(W2, as2, ad2);
    k_agg2<<<N_NODES / 8, 256, 0, s0>>>(b2, out);
}